// round 1
// baseline (speedup 1.0000x reference)
#include <cuda_runtime.h>
#include <math.h>

#define B_   2
#define T_   2048
#define D_   1024
#define H_   16
#define DH   64
#define WIN  128
#define M_   (B_*T_)          // 4096
#define SM_SCALE 0.125f       // 1/sqrt(64)

// ---------------- scratch (device globals; no allocs allowed) ----------------
__device__ __align__(16) float g_q[B_*H_*T_*DH];
__device__ __align__(16) float g_k[B_*H_*T_*DH];
__device__ __align__(16) float g_v[B_*H_*T_*DH];
__device__ __align__(16) float g_ao[B_*T_*D_];
__device__ __align__(16) float g_cos[T_*32];
__device__ __align__(16) float g_sin[T_*32];

// ---------------- tf32 helpers ----------------
__device__ __forceinline__ unsigned f2tf32(float x) {
    unsigned r;
    asm("cvt.rna.tf32.f32 %0, %1;" : "=r"(r) : "f"(x));
    return r;
}

__device__ __forceinline__ void mma_tf32(float (&d)[4], const unsigned (&a)[4], const unsigned (&b)[2]) {
    asm volatile(
        "mma.sync.aligned.m16n8k8.row.col.f32.tf32.tf32.f32 "
        "{%0,%1,%2,%3}, {%4,%5,%6,%7}, {%8,%9}, {%0,%1,%2,%3};\n"
        : "+f"(d[0]), "+f"(d[1]), "+f"(d[2]), "+f"(d[3])
        : "r"(a[0]), "r"(a[1]), "r"(a[2]), "r"(a[3]),
          "r"(b[0]), "r"(b[1]));
}

// ---------------- GEMM: C[m,n] = sum_k A[m,k] * W[n,k] ----------------
// MODE 0: A=query [4096,1024], N=3072 over {Wq,Wk,Wv}; scatter to g_q/g_k/g_v [B,H,T,Dh]
// MODE 1: A=g_ao  [4096,1024], W=Wo, +bias -> out [B,T,D]
#define GBM 128
#define GBN 64
#define GBK 32
#define GST 36   // padded smem row stride (floats): conflict-free fragment loads

template<int MODE>
__global__ void __launch_bounds__(256) gemm_kernel(
    const float* __restrict__ A,
    const float* __restrict__ W0, const float* __restrict__ W1, const float* __restrict__ W2,
    const float* __restrict__ bias, float* __restrict__ out)
{
    __shared__ __align__(16) float As[GBM*GST];
    __shared__ __align__(16) float Bs[GBN*GST];

    const int tid  = threadIdx.x;
    const int lane = tid & 31;
    const int warp = tid >> 5;
    const int wm   = warp & 3;   // 4 warps along M
    const int wn   = warp >> 2;  // 2 warps along N
    const int g    = lane >> 2;
    const int tg   = lane & 3;

    const int m0   = blockIdx.y * GBM;
    const int nblk = blockIdx.x;

    const float* W;
    int n0, proj = 0;
    if (MODE == 0) {
        proj = nblk >> 4;                 // 16 n-blocks per 1024-wide projection
        W = (proj == 0) ? W0 : (proj == 1) ? W1 : W2;
        n0 = (nblk & 15) * GBN;
    } else {
        W = W0;
        n0 = nblk * GBN;
    }
    const float* Aptr = (MODE == 0) ? A : (const float*)g_ao;

    float acc[2][4][4];
    #pragma unroll
    for (int i = 0; i < 2; i++)
        #pragma unroll
        for (int j = 0; j < 4; j++)
            #pragma unroll
            for (int k = 0; k < 4; k++) acc[i][j][k] = 0.f;

    for (int kt = 0; kt < D_/GBK; kt++) {
        const int k0 = kt * GBK;
        __syncthreads();
        // A tile: 128x32 = 1024 float4
        #pragma unroll
        for (int j = 0; j < 4; j++) {
            int id = tid + j*256;
            int m = id >> 3, c4 = (id & 7) << 2;
            float4 v = *(const float4*)&Aptr[(size_t)(m0+m)*D_ + k0 + c4];
            *(float4*)&As[m*GST + c4] = v;
        }
        // B tile: 64x32 = 512 float4
        #pragma unroll
        for (int j = 0; j < 2; j++) {
            int id = tid + j*256;
            int n = id >> 3, c4 = (id & 7) << 2;
            float4 v = *(const float4*)&W[(size_t)(n0+n)*D_ + k0 + c4];
            *(float4*)&Bs[n*GST + c4] = v;
        }
        __syncthreads();

        #pragma unroll
        for (int ks = 0; ks < 4; ks++) {
            const int kb = ks*8;
            unsigned af[2][4], bf[4][2];
            #pragma unroll
            for (int mt = 0; mt < 2; mt++) {
                int rb = wm*32 + mt*16;
                af[mt][0] = f2tf32(As[(rb+g  )*GST + kb+tg  ]);
                af[mt][1] = f2tf32(As[(rb+g+8)*GST + kb+tg  ]);
                af[mt][2] = f2tf32(As[(rb+g  )*GST + kb+tg+4]);
                af[mt][3] = f2tf32(As[(rb+g+8)*GST + kb+tg+4]);
            }
            #pragma unroll
            for (int nt = 0; nt < 4; nt++) {
                int cb = wn*32 + nt*8;
                bf[nt][0] = f2tf32(Bs[(cb+g)*GST + kb+tg  ]);
                bf[nt][1] = f2tf32(Bs[(cb+g)*GST + kb+tg+4]);
            }
            #pragma unroll
            for (int mt = 0; mt < 2; mt++)
                #pragma unroll
                for (int nt = 0; nt < 4; nt++)
                    mma_tf32(acc[mt][nt], af[mt], bf[nt]);
        }
    }

    // epilogue
    #pragma unroll
    for (int mt = 0; mt < 2; mt++) {
        #pragma unroll
        for (int nt = 0; nt < 4; nt++) {
            #pragma unroll
            for (int half = 0; half < 2; half++) {
                int m  = m0 + wm*32 + mt*16 + g + half*8;
                int nl = n0 + wn*32 + nt*8 + tg*2;
                float2 val = make_float2(acc[mt][nt][half*2], acc[mt][nt][half*2+1]);
                if (MODE == 0) {
                    int h = nl >> 6, d = nl & 63;
                    int bb = m >> 11, t = m & (T_-1);
                    float* dst = (proj == 0) ? g_q : (proj == 1) ? g_k : g_v;
                    *(float2*)&dst[(((size_t)bb*H_ + h)*T_ + t)*DH + d] = val;
                } else {
                    val.x += bias[nl];
                    val.y += bias[nl+1];
                    *(float2*)&out[(size_t)m*D_ + nl] = val;
                }
            }
        }
    }
}

// ---------------- RoPE ----------------
__global__ void rope_table_kernel() {
    int i = blockIdx.x*256 + threadIdx.x;   // T_*32
    int t = i >> 5, d = i & 31;
    double inv = exp((-2.0*(double)d/64.0) * log(10000.0));
    double a = (double)t * inv;
    g_cos[i] = (float)cos(a);
    g_sin[i] = (float)sin(a);
}

__global__ void rope_apply_kernel() {
    int i = blockIdx.x*256 + threadIdx.x;   // 2*B*H*T*32
    const int per = B_*H_*T_*32;
    int which = (i >= per);
    int j = i - which*per;
    float* p = which ? g_k : g_q;
    int d  = j & 31;
    int t  = (j >> 5) & (T_-1);
    int bh = j >> 16;                        // / (32*T_)
    size_t base = ((size_t)bh*T_ + t)*DH;
    float c = g_cos[(t<<5)+d], s = g_sin[(t<<5)+d];
    float x1 = p[base+d], x2 = p[base+d+32];
    p[base+d]    = x1*c - x2*s;
    p[base+d+32] = x2*c + x1*s;
}

// ---------------- sliding-window attention (fp32, flash-style) ----------------
#define AST 68   // padded stride for 64-wide tiles (float4-aligned: 68*4 % 16 == 0)

__global__ void __launch_bounds__(256) attn_kernel() {
    __shared__ __align__(16) float KP[64*AST];  // K^T during S-phase, then P
    __shared__ __align__(16) float Vs[64*AST];

    const int tid = threadIdx.x;
    const int b = blockIdx.z, h = blockIdx.y, qt = blockIdx.x;
    const int qstart = qt << 6;
    const int r  = tid >> 2;       // query row within tile (0..63)
    const int cg = tid & 3;        // column/dim group
    const int d0 = cg << 4;
    const int lane = tid & 31;
    const int i_q = qstart + r;
    const size_t bhbase = ((size_t)(b*H_ + h))*T_*DH;

    // Q row held in registers, distributed across the 4 lanes of the quad
    float q[16];
    #pragma unroll
    for (int u = 0; u < 4; u++) {
        float4 v = *(const float4*)&g_q[bhbase + (size_t)i_q*DH + d0 + u*4];
        q[u*4+0]=v.x; q[u*4+1]=v.y; q[u*4+2]=v.z; q[u*4+3]=v.w;
    }

    float o[16];
    #pragma unroll
    for (int u = 0; u < 16; u++) o[u] = 0.f;
    float m_i = -1e30f, l_i = 0.f;

    const int clo = (qt >= 2) ? qt-2 : 0;
    for (int ck = clo; ck <= qt; ck++) {
        const int kstart = ck << 6;
        __syncthreads();
        // load K transposed (KP[k][c]) and V normal (Vs[c][d])
        #pragma unroll
        for (int j = 0; j < 4; j++) {
            int id = tid + j*256;
            int c = id >> 4, k4 = (id & 15) << 2;
            float4 kv = *(const float4*)&g_k[bhbase + (size_t)(kstart+c)*DH + k4];
            KP[(k4+0)*AST + c] = kv.x;
            KP[(k4+1)*AST + c] = kv.y;
            KP[(k4+2)*AST + c] = kv.z;
            KP[(k4+3)*AST + c] = kv.w;
            float4 vv = *(const float4*)&g_v[bhbase + (size_t)(kstart+c)*DH + k4];
            *(float4*)&Vs[c*AST + k4] = vv;
        }
        __syncthreads();

        // S = Q K^T for this thread's 16 key-columns
        float s[16];
        #pragma unroll
        for (int u = 0; u < 16; u++) s[u] = 0.f;
        #pragma unroll 16
        for (int k = 0; k < 64; k++) {
            float qv = __shfl_sync(0xffffffffu, q[k & 15], (lane & ~3) | (k >> 4));
            float kv[16];
            const float4* kr = (const float4*)&KP[k*AST + d0];
            *(float4*)&kv[0]  = kr[0];
            *(float4*)&kv[4]  = kr[1];
            *(float4*)&kv[8]  = kr[2];
            *(float4*)&kv[12] = kr[3];
            #pragma unroll
            for (int cc = 0; cc < 16; cc++) s[cc] += qv * kv[cc];
        }

        // mask + scale, row max
        float mx = -1e30f;
        #pragma unroll
        for (int cc = 0; cc < 16; cc++) {
            int jk = kstart + d0 + cc;
            bool valid = (jk <= i_q) && (jk >= i_q - (WIN-1));
            s[cc] = valid ? s[cc]*SM_SCALE : -1e30f;
            mx = fmaxf(mx, s[cc]);
        }
        mx = fmaxf(mx, __shfl_xor_sync(0xffffffffu, mx, 1));
        mx = fmaxf(mx, __shfl_xor_sync(0xffffffffu, mx, 2));
        float m_new = fmaxf(m_i, mx);
        float corr  = __expf(m_i - m_new);

        float rs = 0.f;
        #pragma unroll
        for (int cc = 0; cc < 16; cc++) {
            s[cc] = (s[cc] > -1e29f) ? __expf(s[cc] - m_new) : 0.f;
            rs += s[cc];
        }
        rs += __shfl_xor_sync(0xffffffffu, rs, 1);
        rs += __shfl_xor_sync(0xffffffffu, rs, 2);
        l_i = l_i*corr + rs;
        m_i = m_new;
        #pragma unroll
        for (int u = 0; u < 16; u++) o[u] *= corr;

        __syncthreads();   // everyone done reading KP as K^T
        // write P (reuse KP as Ps[r][c])
        #pragma unroll
        for (int u = 0; u < 4; u++)
            *(float4*)&KP[r*AST + d0 + u*4] = make_float4(s[u*4], s[u*4+1], s[u*4+2], s[u*4+3]);
        __syncthreads();

        // O += P V
        #pragma unroll 16
        for (int c = 0; c < 64; c++) {
            float pv = KP[r*AST + c];
            float vv[16];
            const float4* vr = (const float4*)&Vs[c*AST + d0];
            *(float4*)&vv[0]  = vr[0];
            *(float4*)&vv[4]  = vr[1];
            *(float4*)&vv[8]  = vr[2];
            *(float4*)&vv[12] = vr[3];
            #pragma unroll
            for (int dd = 0; dd < 16; dd++) o[dd] += pv * vv[dd];
        }
    }

    const float inv = 1.0f / l_i;
    const size_t obase = ((size_t)(b*T_ + i_q))*D_ + h*DH + d0;
    #pragma unroll
    for (int u = 0; u < 4; u++)
        *(float4*)&g_ao[obase + u*4] =
            make_float4(o[u*4]*inv, o[u*4+1]*inv, o[u*4+2]*inv, o[u*4+3]*inv);
}

// ---------------- launch ----------------
extern "C" void kernel_launch(void* const* d_in, const int* in_sizes, int n_in,
                              void* d_out, int out_size) {
    const float* query = (const float*)d_in[0];
    const float* Wq    = (const float*)d_in[1];
    const float* Wk    = (const float*)d_in[2];
    const float* Wv    = (const float*)d_in[3];
    const float* Wo    = (const float*)d_in[4];
    const float* bo    = (const float*)d_in[5];
    float* out = (float*)d_out;

    rope_table_kernel<<<(T_*32)/256, 256>>>();
    gemm_kernel<0><<<dim3(48, M_/GBM), 256>>>(query, Wq, Wk, Wv, nullptr, nullptr);
    rope_apply_kernel<<<(2*B_*H_*T_*32)/256, 256>>>();
    attn_kernel<<<dim3(T_/64, H_, B_), 256>>>();
    gemm_kernel<1><<<dim3(D_/GBN, M_/GBM), 256>>>(nullptr, Wo, nullptr, nullptr, bo, out);
}

// round 3
// speedup vs baseline: 2.0271x; 2.0271x over previous
#include <cuda_runtime.h>
#include <math.h>

#define B_   2
#define T_   2048
#define D_   1024
#define H_   16
#define DH   64
#define WIN  128
#define M_   (B_*T_)          // 4096
#define SM_SCALE 0.125f       // 1/sqrt(64)

// ---------------- scratch ----------------
__device__ __align__(16) float g_q[B_*H_*T_*DH];
__device__ __align__(16) float g_k[B_*H_*T_*DH];
__device__ __align__(16) float g_v[B_*H_*T_*DH];
__device__ __align__(16) float g_ao[B_*T_*D_];
__device__ __align__(16) float g_cos[T_*32];
__device__ __align__(16) float g_sin[T_*32];

// ---------------- tf32 helpers ----------------
__device__ __forceinline__ unsigned f2tf32(float x) {
    unsigned r;
    asm("cvt.rna.tf32.f32 %0, %1;" : "=r"(r) : "f"(x));
    return r;
}

__device__ __forceinline__ void mma_tf32(float (&d)[4], const unsigned (&a)[4], const unsigned (&b)[2]) {
    asm volatile(
        "mma.sync.aligned.m16n8k8.row.col.f32.tf32.tf32.f32 "
        "{%0,%1,%2,%3}, {%4,%5,%6,%7}, {%8,%9}, {%0,%1,%2,%3};\n"
        : "+f"(d[0]), "+f"(d[1]), "+f"(d[2]), "+f"(d[3])
        : "r"(a[0]), "r"(a[1]), "r"(a[2]), "r"(a[3]),
          "r"(b[0]), "r"(b[1]));
}

// ---------------- GEMM (register-prefetch pipelined) ----------------
#define GBM 128
#define GBN 64
#define GBK 32
#define GST 36

template<int MODE>
__global__ void __launch_bounds__(256) gemm_kernel(
    const float* __restrict__ A,
    const float* __restrict__ W0, const float* __restrict__ W1, const float* __restrict__ W2,
    const float* __restrict__ bias, float* __restrict__ out)
{
    __shared__ __align__(16) unsigned As[GBM*GST];
    __shared__ __align__(16) unsigned Bs[GBN*GST];

    const int tid  = threadIdx.x;
    const int lane = tid & 31;
    const int warp = tid >> 5;
    const int wm   = warp & 3;
    const int wn   = warp >> 2;
    const int g    = lane >> 2;
    const int tg   = lane & 3;

    const int m0   = blockIdx.y * GBM;
    const int nblk = blockIdx.x;

    const float* W;
    int n0, proj = 0;
    if (MODE == 0) {
        proj = nblk >> 4;
        W = (proj == 0) ? W0 : (proj == 1) ? W1 : W2;
        n0 = (nblk & 15) * GBN;
    } else {
        W = W0;
        n0 = nblk * GBN;
    }
    const float* Aptr = (MODE == 0) ? A : (const float*)g_ao;

    const int am = tid >> 3, ac = (tid & 7) << 2;
    float acc[2][4][4];
    #pragma unroll
    for (int i = 0; i < 2; i++)
        #pragma unroll
        for (int j = 0; j < 4; j++)
            #pragma unroll
            for (int k = 0; k < 4; k++) acc[i][j][k] = 0.f;

    float4 ra[4], rb[2];
    #pragma unroll
    for (int j = 0; j < 4; j++)
        ra[j] = *(const float4*)&Aptr[(size_t)(m0 + am + j*32)*D_ + ac];
    #pragma unroll
    for (int j = 0; j < 2; j++)
        rb[j] = *(const float4*)&W[(size_t)(n0 + am + j*32)*D_ + ac];

    for (int kt = 0; kt < D_/GBK; kt++) {
        __syncthreads();
        #pragma unroll
        for (int j = 0; j < 4; j++) {
            unsigned* p = &As[(am + j*32)*GST + ac];
            p[0]=f2tf32(ra[j].x); p[1]=f2tf32(ra[j].y); p[2]=f2tf32(ra[j].z); p[3]=f2tf32(ra[j].w);
        }
        #pragma unroll
        for (int j = 0; j < 2; j++) {
            unsigned* p = &Bs[(am + j*32)*GST + ac];
            p[0]=f2tf32(rb[j].x); p[1]=f2tf32(rb[j].y); p[2]=f2tf32(rb[j].z); p[3]=f2tf32(rb[j].w);
        }
        __syncthreads();

        if (kt + 1 < D_/GBK) {
            const int k0 = (kt+1) * GBK;
            #pragma unroll
            for (int j = 0; j < 4; j++)
                ra[j] = *(const float4*)&Aptr[(size_t)(m0 + am + j*32)*D_ + k0 + ac];
            #pragma unroll
            for (int j = 0; j < 2; j++)
                rb[j] = *(const float4*)&W[(size_t)(n0 + am + j*32)*D_ + k0 + ac];
        }

        #pragma unroll
        for (int ks = 0; ks < 4; ks++) {
            const int kb = ks*8;
            unsigned af[2][4], bf[4][2];
            #pragma unroll
            for (int mt = 0; mt < 2; mt++) {
                int rbase = wm*32 + mt*16;
                af[mt][0] = As[(rbase+g  )*GST + kb+tg  ];
                af[mt][1] = As[(rbase+g+8)*GST + kb+tg  ];
                af[mt][2] = As[(rbase+g  )*GST + kb+tg+4];
                af[mt][3] = As[(rbase+g+8)*GST + kb+tg+4];
            }
            #pragma unroll
            for (int nt = 0; nt < 4; nt++) {
                int cb = wn*32 + nt*8;
                bf[nt][0] = Bs[(cb+g)*GST + kb+tg  ];
                bf[nt][1] = Bs[(cb+g)*GST + kb+tg+4];
            }
            #pragma unroll
            for (int mt = 0; mt < 2; mt++)
                #pragma unroll
                for (int nt = 0; nt < 4; nt++)
                    mma_tf32(acc[mt][nt], af[mt], bf[nt]);
        }
    }

    #pragma unroll
    for (int mt = 0; mt < 2; mt++) {
        #pragma unroll
        for (int nt = 0; nt < 4; nt++) {
            #pragma unroll
            for (int half = 0; half < 2; half++) {
                int m  = m0 + wm*32 + mt*16 + g + half*8;
                int nl = n0 + wn*32 + nt*8 + tg*2;
                float2 val = make_float2(acc[mt][nt][half*2], acc[mt][nt][half*2+1]);
                if (MODE == 0) {
                    int h = nl >> 6, d = nl & 63;
                    int bb = m >> 11, t = m & (T_-1);
                    float* dst = (proj == 0) ? g_q : (proj == 1) ? g_k : g_v;
                    *(float2*)&dst[(((size_t)bb*H_ + h)*T_ + t)*DH + d] = val;
                } else {
                    val.x += bias[nl];
                    val.y += bias[nl+1];
                    *(float2*)&out[(size_t)m*D_ + nl] = val;
                }
            }
        }
    }
}

// ---------------- RoPE ----------------
__global__ void rope_table_kernel() {
    int i = blockIdx.x*256 + threadIdx.x;
    int t = i >> 5, d = i & 31;
    double inv = exp((-2.0*(double)d/64.0) * log(10000.0));
    double a = (double)t * inv;
    g_cos[i] = (float)cos(a);
    g_sin[i] = (float)sin(a);
}

__global__ void rope_apply_kernel() {
    int i = blockIdx.x*256 + threadIdx.x;
    const int per = B_*H_*T_*32;
    int which = (i >= per);
    int j = i - which*per;
    float* p = which ? g_k : g_q;
    int d  = j & 31;
    int t  = (j >> 5) & (T_-1);
    int bh = j >> 16;
    size_t base = ((size_t)bh*T_ + t)*DH;
    float c = g_cos[(t<<5)+d], s = g_sin[(t<<5)+d];
    float x1 = p[base+d], x2 = p[base+d+32];
    p[base+d]    = x1*c - x2*s;
    p[base+d+32] = x2*c + x1*s;
}

// ---------------- tensor-core sliding-window attention ----------------
#define KST 68
#define VST 72

__global__ void __launch_bounds__(128) attn_kernel() {
    __shared__ __align__(16) unsigned Ks[64*KST];   // K chunk (tf32), reused as P
    __shared__ __align__(16) unsigned Vs[64*VST];   // V chunk (tf32)

    const int tid  = threadIdx.x;
    const int lane = tid & 31;
    const int warp = tid >> 5;
    const int g    = lane >> 2;
    const int t4   = lane & 3;

    const int b = blockIdx.z, h = blockIdx.y, qt = blockIdx.x;
    const int qstart = qt << 6;
    const int w16 = warp << 4;
    const int r0 = qstart + w16 + g;
    const int r1 = r0 + 8;
    const size_t bhbase = ((size_t)(b*H_ + h))*T_*DH;

    unsigned qf[8][4];
    {
        const float* Q = &g_q[bhbase + (size_t)(qstart + w16)*DH];
        #pragma unroll
        for (int ks = 0; ks < 8; ks++) {
            int kb = ks*8;
            qf[ks][0] = f2tf32(SM_SCALE * Q[(size_t)(g  )*DH + kb + t4    ]);
            qf[ks][1] = f2tf32(SM_SCALE * Q[(size_t)(g+8)*DH + kb + t4    ]);
            qf[ks][2] = f2tf32(SM_SCALE * Q[(size_t)(g  )*DH + kb + t4 + 4]);
            qf[ks][3] = f2tf32(SM_SCALE * Q[(size_t)(g+8)*DH + kb + t4 + 4]);
        }
    }

    float o[8][4];
    #pragma unroll
    for (int nt = 0; nt < 8; nt++)
        #pragma unroll
        for (int c = 0; c < 4; c++) o[nt][c] = 0.f;
    float m0v = -1e30f, m1v = -1e30f, l0 = 0.f, l1 = 0.f;

    const int clo = (qt >= 2) ? qt-2 : 0;
    for (int ck = clo; ck <= qt; ck++) {
        const int kstart = ck << 6;
        __syncthreads();
        // load full 64-row K,V chunk: 1024 float4s across 128 threads => j<8
        #pragma unroll
        for (int j = 0; j < 8; j++) {
            int id = tid + j*128;
            int pos = id >> 4, d4 = (id & 15) << 2;
            float4 kv = *(const float4*)&g_k[bhbase + (size_t)(kstart+pos)*DH + d4];
            unsigned* kp = &Ks[pos*KST + d4];
            kp[0]=f2tf32(kv.x); kp[1]=f2tf32(kv.y); kp[2]=f2tf32(kv.z); kp[3]=f2tf32(kv.w);
            float4 vv = *(const float4*)&g_v[bhbase + (size_t)(kstart+pos)*DH + d4];
            unsigned* vp = &Vs[pos*VST + d4];
            vp[0]=f2tf32(vv.x); vp[1]=f2tf32(vv.y); vp[2]=f2tf32(vv.z); vp[3]=f2tf32(vv.w);
        }
        __syncthreads();

        // S = Q K^T  (16 x 64 per warp)
        float s[8][4];
        #pragma unroll
        for (int nt = 0; nt < 8; nt++)
            #pragma unroll
            for (int c = 0; c < 4; c++) s[nt][c] = 0.f;
        #pragma unroll
        for (int ks = 0; ks < 8; ks++) {
            const int kb = ks*8;
            #pragma unroll
            for (int nt = 0; nt < 8; nt++) {
                unsigned bfrag[2];
                bfrag[0] = Ks[(nt*8 + g)*KST + kb + t4];
                bfrag[1] = Ks[(nt*8 + g)*KST + kb + t4 + 4];
                mma_tf32(s[nt], qf[ks], bfrag);
            }
        }

        // mask + online softmax
        float mx0 = -1e30f, mx1 = -1e30f;
        #pragma unroll
        for (int nt = 0; nt < 8; nt++) {
            int j0 = kstart + nt*8 + 2*t4;
            int j1 = j0 + 1;
            if (!(j0 <= r0 && j0 >= r0 - (WIN-1))) s[nt][0] = -1e30f;
            if (!(j1 <= r0 && j1 >= r0 - (WIN-1))) s[nt][1] = -1e30f;
            if (!(j0 <= r1 && j0 >= r1 - (WIN-1))) s[nt][2] = -1e30f;
            if (!(j1 <= r1 && j1 >= r1 - (WIN-1))) s[nt][3] = -1e30f;
            mx0 = fmaxf(mx0, fmaxf(s[nt][0], s[nt][1]));
            mx1 = fmaxf(mx1, fmaxf(s[nt][2], s[nt][3]));
        }
        mx0 = fmaxf(mx0, __shfl_xor_sync(0xffffffffu, mx0, 1));
        mx0 = fmaxf(mx0, __shfl_xor_sync(0xffffffffu, mx0, 2));
        mx1 = fmaxf(mx1, __shfl_xor_sync(0xffffffffu, mx1, 1));
        mx1 = fmaxf(mx1, __shfl_xor_sync(0xffffffffu, mx1, 2));

        float mn0 = fmaxf(m0v, mx0), mn1 = fmaxf(m1v, mx1);
        float c0 = __expf(m0v - mn0), c1 = __expf(m1v - mn1);
        float rs0 = 0.f, rs1 = 0.f;
        #pragma unroll
        for (int nt = 0; nt < 8; nt++) {
            s[nt][0] = (s[nt][0] > -1e29f) ? __expf(s[nt][0] - mn0) : 0.f;
            s[nt][1] = (s[nt][1] > -1e29f) ? __expf(s[nt][1] - mn0) : 0.f;
            s[nt][2] = (s[nt][2] > -1e29f) ? __expf(s[nt][2] - mn1) : 0.f;
            s[nt][3] = (s[nt][3] > -1e29f) ? __expf(s[nt][3] - mn1) : 0.f;
            rs0 += s[nt][0] + s[nt][1];
            rs1 += s[nt][2] + s[nt][3];
        }
        rs0 += __shfl_xor_sync(0xffffffffu, rs0, 1);
        rs0 += __shfl_xor_sync(0xffffffffu, rs0, 2);
        rs1 += __shfl_xor_sync(0xffffffffu, rs1, 1);
        rs1 += __shfl_xor_sync(0xffffffffu, rs1, 2);
        l0 = l0*c0 + rs0;  l1 = l1*c1 + rs1;
        m0v = mn0;         m1v = mn1;
        #pragma unroll
        for (int nt = 0; nt < 8; nt++) {
            o[nt][0] *= c0; o[nt][1] *= c0;
            o[nt][2] *= c1; o[nt][3] *= c1;
        }

        __syncthreads();   // all warps finished reading Ks as K
        #pragma unroll
        for (int nt = 0; nt < 8; nt++) {
            unsigned* p0 = &Ks[(w16 + g    )*KST + nt*8 + 2*t4];
            unsigned* p1 = &Ks[(w16 + g + 8)*KST + nt*8 + 2*t4];
            p0[0] = f2tf32(s[nt][0]); p0[1] = f2tf32(s[nt][1]);
            p1[0] = f2tf32(s[nt][2]); p1[1] = f2tf32(s[nt][3]);
        }
        __syncwarp();

        // O += P V
        #pragma unroll
        for (int ks = 0; ks < 8; ks++) {
            const int kb = ks*8;
            unsigned pa[4];
            pa[0] = Ks[(w16 + g    )*KST + kb + t4];
            pa[1] = Ks[(w16 + g + 8)*KST + kb + t4];
            pa[2] = Ks[(w16 + g    )*KST + kb + t4 + 4];
            pa[3] = Ks[(w16 + g + 8)*KST + kb + t4 + 4];
            #pragma unroll
            for (int nt = 0; nt < 8; nt++) {
                unsigned vb[2];
                vb[0] = Vs[(kb + t4    )*VST + nt*8 + g];
                vb[1] = Vs[(kb + t4 + 4)*VST + nt*8 + g];
                mma_tf32(o[nt], pa, vb);
            }
        }
    }

    const float inv0 = 1.0f / l0, inv1 = 1.0f / l1;
    float* out0 = &g_ao[(size_t)(b*T_ + r0)*D_ + h*DH];
    float* out1 = &g_ao[(size_t)(b*T_ + r1)*D_ + h*DH];
    #pragma unroll
    for (int nt = 0; nt < 8; nt++) {
        int d = nt*8 + 2*t4;
        *(float2*)&out0[d] = make_float2(o[nt][0]*inv0, o[nt][1]*inv0);
        *(float2*)&out1[d] = make_float2(o[nt][2]*inv1, o[nt][3]*inv1);
    }
}

// ---------------- launch ----------------
extern "C" void kernel_launch(void* const* d_in, const int* in_sizes, int n_in,
                              void* d_out, int out_size) {
    const float* query = (const float*)d_in[0];
    const float* Wq    = (const float*)d_in[1];
    const float* Wk    = (const float*)d_in[2];
    const float* Wv    = (const float*)d_in[3];
    const float* Wo    = (const float*)d_in[4];
    const float* bo    = (const float*)d_in[5];
    float* out = (float*)d_out;

    rope_table_kernel<<<(T_*32)/256, 256>>>();
    gemm_kernel<0><<<dim3(48, M_/GBM), 256>>>(query, Wq, Wk, Wv, nullptr, nullptr);
    rope_apply_kernel<<<(2*B_*H_*T_*32)/256, 256>>>();
    attn_kernel<<<dim3(T_/64, H_, B_), 128>>>();
    gemm_kernel<1><<<dim3(D_/GBN, M_/GBM), 256>>>(nullptr, Wo, nullptr, nullptr, bo, out);
}

// round 6
// speedup vs baseline: 2.2904x; 1.1299x over previous
#include <cuda_runtime.h>
#include <math.h>
#include <stdint.h>

#define B_   2
#define T_   2048
#define D_   1024
#define H_   16
#define DH   64
#define WIN  128
#define M_   (B_*T_)          // 4096
#define SM_SCALE 0.125f

// ---------------- scratch ----------------
__device__ __align__(16) float g_q[B_*H_*T_*DH];
__device__ __align__(16) float g_k[B_*H_*T_*DH];
__device__ __align__(16) float g_v[B_*H_*T_*DH];
__device__ __align__(16) float g_ao[B_*T_*D_];
__device__ __align__(16) float g_qr[M_*D_];        // tf32-rounded query
__device__ __align__(16) float g_wr[4*D_*D_];      // tf32-rounded Wq,Wk,Wv,Wo
__device__ __align__(16) float g_cos[T_*32];
__device__ __align__(16) float g_sin[T_*32];

// ---------------- helpers ----------------
__device__ __forceinline__ unsigned f2tf32(float x) {
    unsigned r;
    asm("cvt.rna.tf32.f32 %0, %1;" : "=r"(r) : "f"(x));
    return r;
}
__device__ __forceinline__ float tfr(float x) { return __uint_as_float(f2tf32(x)); }

__device__ __forceinline__ uint32_t smem_u32(const void* p) {
    uint32_t a;
    asm("{ .reg .u64 t; cvta.to.shared.u64 t, %1; cvt.u32.u64 %0, t; }" : "=r"(a) : "l"(p));
    return a;
}

#define CP_ASYNC16(dst, src) \
    asm volatile("cp.async.cg.shared.global [%0], [%1], 16;" :: "r"(dst), "l"(src))
#define CP_COMMIT() asm volatile("cp.async.commit_group;" ::: "memory")
#define CP_WAIT1()  asm volatile("cp.async.wait_group 1;"  ::: "memory")

__device__ __forceinline__ void mma_tf32(float (&d)[4], const unsigned (&a)[4], const unsigned (&b)[2]) {
    asm volatile(
        "mma.sync.aligned.m16n8k8.row.col.f32.tf32.tf32.f32 "
        "{%0,%1,%2,%3}, {%4,%5,%6,%7}, {%8,%9}, {%0,%1,%2,%3};\n"
        : "+f"(d[0]), "+f"(d[1]), "+f"(d[2]), "+f"(d[3])
        : "r"(a[0]), "r"(a[1]), "r"(a[2]), "r"(a[3]), "r"(b[0]), "r"(b[1]));
}

// ---------------- pre-round inputs to tf32 (RNA) so mma truncation is exact ----------------
__device__ __forceinline__ float4 rt4(float4 v) {
    return make_float4(tfr(v.x), tfr(v.y), tfr(v.z), tfr(v.w));
}
__global__ void round_kernel(const float4* __restrict__ q, const float4* __restrict__ wq,
                             const float4* __restrict__ wk, const float4* __restrict__ wv,
                             const float4* __restrict__ wo) {
    int id = blockIdx.x*256 + threadIdx.x;
    float4* qr = (float4*)g_qr;
    float4* wr = (float4*)g_wr;
    const int WQ4 = D_*D_/4;
    if (id < M_*D_/4) qr[id] = rt4(q[id]);
    if (id < WQ4) {
        wr[id        ] = rt4(wq[id]);
        wr[id +   WQ4] = rt4(wk[id]);
        wr[id + 2*WQ4] = rt4(wv[id]);
        wr[id + 3*WQ4] = rt4(wo[id]);
    }
}

// ---------------- RoPE table ----------------
__global__ void rope_table_kernel() {
    int i = blockIdx.x*256 + threadIdx.x;
    int t = i >> 5, d = i & 31;
    double inv = exp((-2.0*(double)d/64.0) * log(10000.0));
    double a = (double)t * inv;
    g_cos[i] = (float)cos(a);
    g_sin[i] = (float)sin(a);
}

// ---------------- cp.async 3-stage tf32 GEMM: C[m,n] = sum_k A[m,k] W[n,k] ----------------
// MODE 0: A=g_qr, W=g_wr[proj]; epilogue: scatter + fused RoPE(q,k) -> g_q/g_k/g_v
// MODE 1: A=g_ao, W=g_wr[3], +bias -> out
#define GBM 128
#define GBN 128
#define GBK 32
#define NSTG 3
#define NCH  (D_/GBK)               // 32
#define SST  36                      // padded row stride (floats)
#define A_ELE (GBM*SST)              // 4608 floats
#define B_ELE (GBN*SST)              // 4608 floats
#define STG_BYTES ((A_ELE + B_ELE)*4)   // 36864
#define SMEM_TOT (NSTG*STG_BYTES)       // 110592

__device__ __forceinline__ void load_stage(uint32_t stg_b, const float* __restrict__ Aq,
                                           const float* __restrict__ Wm,
                                           int m0, int n0, int k0, int tid) {
    // A: 128 rows x 32 floats = 1024 x 16B chunks; B same. 256 threads -> 4 chunks each.
    #pragma unroll
    for (int i = 0; i < 4; i++) {
        int id = tid + i*256;
        int row = id >> 3, c4 = (id & 7) << 2;
        uint32_t dst = stg_b + (uint32_t)(row*SST + c4)*4;
        CP_ASYNC16(dst, Aq + (size_t)(m0+row)*D_ + k0 + c4);
    }
    uint32_t bb = stg_b + A_ELE*4;
    #pragma unroll
    for (int i = 0; i < 4; i++) {
        int id = tid + i*256;
        int row = id >> 3, c4 = (id & 7) << 2;
        uint32_t dst = bb + (uint32_t)(row*SST + c4)*4;
        CP_ASYNC16(dst, Wm + (size_t)(n0+row)*D_ + k0 + c4);
    }
}

template<int MODE>
__global__ void __launch_bounds__(256, 2) gemm_kernel(const float* __restrict__ bias,
                                                      float* __restrict__ out) {
    extern __shared__ __align__(16) unsigned smem[];
    uint32_t sb = smem_u32(smem);

    const int tid  = threadIdx.x;
    const int lane = tid & 31;
    const int warp = tid >> 5;
    const int wm   = warp & 3;     // 4 warps along M (32 rows each)
    const int wn   = warp >> 2;    // 2 warps along N (64 cols each)
    const int g    = lane >> 2;
    const int tg   = lane & 3;

    const int m0   = blockIdx.y * GBM;
    const int nblk = blockIdx.x;

    int proj, n0;
    const float *Aptr, *W;
    if (MODE == 0) {
        proj = nblk >> 3;  n0 = (nblk & 7) * GBN;
        Aptr = g_qr;  W = g_wr + (size_t)proj * D_ * D_;
    } else {
        proj = 3;  n0 = nblk * GBN;
        Aptr = g_ao;  W = g_wr + (size_t)3 * D_ * D_;
    }

    float acc[2][8][4];
    #pragma unroll
    for (int i = 0; i < 2; i++)
        #pragma unroll
        for (int j = 0; j < 8; j++)
            #pragma unroll
            for (int k = 0; k < 4; k++) acc[i][j][k] = 0.f;

    // prologue: stages 0,1
    load_stage(sb,             Aptr, W, m0, n0, 0,   tid); CP_COMMIT();
    load_stage(sb + STG_BYTES, Aptr, W, m0, n0, GBK, tid); CP_COMMIT();

    for (int kt = 0; kt < NCH; kt++) {
        CP_WAIT1();
        __syncthreads();
        const int c2 = kt + NSTG - 1;
        if (c2 < NCH) {
            int s2 = c2 % NSTG;
            load_stage(sb + s2*STG_BYTES, Aptr, W, m0, n0, c2*GBK, tid);
        }
        CP_COMMIT();

        const unsigned* As = smem + (kt % NSTG)*(A_ELE + B_ELE);
        const unsigned* Bs = As + A_ELE;

        #pragma unroll
        for (int ks = 0; ks < 4; ks++) {
            const int kb = ks*8;
            unsigned af[2][4], bf[8][2];
            #pragma unroll
            for (int mt = 0; mt < 2; mt++) {
                int rbase = wm*32 + mt*16;
                af[mt][0] = As[(rbase+g  )*SST + kb+tg  ];
                af[mt][1] = As[(rbase+g+8)*SST + kb+tg  ];
                af[mt][2] = As[(rbase+g  )*SST + kb+tg+4];
                af[mt][3] = As[(rbase+g+8)*SST + kb+tg+4];
            }
            #pragma unroll
            for (int nt = 0; nt < 8; nt++) {
                int cb = wn*64 + nt*8;
                bf[nt][0] = Bs[(cb+g)*SST + kb+tg  ];
                bf[nt][1] = Bs[(cb+g)*SST + kb+tg+4];
            }
            #pragma unroll
            for (int mt = 0; mt < 2; mt++)
                #pragma unroll
                for (int nt = 0; nt < 8; nt++)
                    mma_tf32(acc[mt][nt], af[mt], bf[nt]);
        }
    }

    // -------- epilogue --------
    #pragma unroll
    for (int mt = 0; mt < 2; mt++) {
        #pragma unroll
        for (int half = 0; half < 2; half++) {
            int m = m0 + wm*32 + mt*16 + g + half*8;
            int t = m & (T_-1), bb = m >> 11;
            if (MODE == 0) {
                int h = (n0 + wn*64) >> 6;
                float* dst = (proj == 0) ? g_q : (proj == 1) ? g_k : g_v;
                float* row = &dst[(((size_t)bb*H_ + h)*T_ + t)*DH];
                if (proj < 2) {
                    #pragma unroll
                    for (int nt = 0; nt < 4; nt++) {
                        int d0 = nt*8 + 2*tg;
                        float2 cc = *(const float2*)&g_cos[t*32 + d0];
                        float2 ss = *(const float2*)&g_sin[t*32 + d0];
                        float x1a = acc[mt][nt  ][half*2], x1b = acc[mt][nt  ][half*2+1];
                        float x2a = acc[mt][nt+4][half*2], x2b = acc[mt][nt+4][half*2+1];
                        *(float2*)&row[d0]      = make_float2(x1a*cc.x - x2a*ss.x,
                                                              x1b*cc.y - x2b*ss.y);
                        *(float2*)&row[d0 + 32] = make_float2(x2a*cc.x + x1a*ss.x,
                                                              x2b*cc.y + x1b*ss.y);
                    }
                } else {
                    #pragma unroll
                    for (int nt = 0; nt < 8; nt++) {
                        int d0 = nt*8 + 2*tg;
                        *(float2*)&row[d0] = make_float2(acc[mt][nt][half*2], acc[mt][nt][half*2+1]);
                    }
                }
            } else {
                int ncol = n0 + wn*64;
                float* orow = &out[(size_t)m*D_ + ncol];
                #pragma unroll
                for (int nt = 0; nt < 8; nt++) {
                    int nl = nt*8 + 2*tg;
                    *(float2*)&orow[nl] = make_float2(acc[mt][nt][half*2]   + bias[ncol+nl],
                                                      acc[mt][nt][half*2+1] + bias[ncol+nl+1]);
                }
            }
        }
    }
}

// ---------------- tensor-core sliding-window attention (known-good @55.9us) ----------------
#define KST 68
#define VST 72

__global__ void __launch_bounds__(128) attn_kernel() {
    __shared__ __align__(16) unsigned Ks[64*KST];
    __shared__ __align__(16) unsigned Vs[64*VST];

    const int tid  = threadIdx.x;
    const int lane = tid & 31;
    const int warp = tid >> 5;
    const int g    = lane >> 2;
    const int t4   = lane & 3;

    const int b = blockIdx.z, h = blockIdx.y, qt = blockIdx.x;
    const int qstart = qt << 6;
    const int w16 = warp << 4;
    const int r0 = qstart + w16 + g;
    const int r1 = r0 + 8;
    const size_t bhbase = ((size_t)(b*H_ + h))*T_*DH;

    unsigned qf[8][4];
    {
        const float* Q = &g_q[bhbase + (size_t)(qstart + w16)*DH];
        #pragma unroll
        for (int ks = 0; ks < 8; ks++) {
            int kb = ks*8;
            qf[ks][0] = f2tf32(SM_SCALE * Q[(size_t)(g  )*DH + kb + t4    ]);
            qf[ks][1] = f2tf32(SM_SCALE * Q[(size_t)(g+8)*DH + kb + t4    ]);
            qf[ks][2] = f2tf32(SM_SCALE * Q[(size_t)(g  )*DH + kb + t4 + 4]);
            qf[ks][3] = f2tf32(SM_SCALE * Q[(size_t)(g+8)*DH + kb + t4 + 4]);
        }
    }

    float o[8][4];
    #pragma unroll
    for (int nt = 0; nt < 8; nt++)
        #pragma unroll
        for (int c = 0; c < 4; c++) o[nt][c] = 0.f;
    float m0v = -1e30f, m1v = -1e30f, l0 = 0.f, l1 = 0.f;

    const int clo = (qt >= 2) ? qt-2 : 0;
    for (int ck = clo; ck <= qt; ck++) {
        const int kstart = ck << 6;
        __syncthreads();
        #pragma unroll
        for (int j = 0; j < 8; j++) {
            int id = tid + j*128;
            int pos = id >> 4, d4 = (id & 15) << 2;
            float4 kv = *(const float4*)&g_k[bhbase + (size_t)(kstart+pos)*DH + d4];
            unsigned* kp = &Ks[pos*KST + d4];
            kp[0]=f2tf32(kv.x); kp[1]=f2tf32(kv.y); kp[2]=f2tf32(kv.z); kp[3]=f2tf32(kv.w);
            float4 vv = *(const float4*)&g_v[bhbase + (size_t)(kstart+pos)*DH + d4];
            unsigned* vp = &Vs[pos*VST + d4];
            vp[0]=f2tf32(vv.x); vp[1]=f2tf32(vv.y); vp[2]=f2tf32(vv.z); vp[3]=f2tf32(vv.w);
        }
        __syncthreads();

        float s[8][4];
        #pragma unroll
        for (int nt = 0; nt < 8; nt++)
            #pragma unroll
            for (int c = 0; c < 4; c++) s[nt][c] = 0.f;
        #pragma unroll
        for (int ks = 0; ks < 8; ks++) {
            const int kb = ks*8;
            #pragma unroll
            for (int nt = 0; nt < 8; nt++) {
                unsigned bfrag[2];
                bfrag[0] = Ks[(nt*8 + g)*KST + kb + t4];
                bfrag[1] = Ks[(nt*8 + g)*KST + kb + t4 + 4];
                mma_tf32(s[nt], qf[ks], bfrag);
            }
        }

        float mx0 = -1e30f, mx1 = -1e30f;
        #pragma unroll
        for (int nt = 0; nt < 8; nt++) {
            int j0 = kstart + nt*8 + 2*t4;
            int j1 = j0 + 1;
            if (!(j0 <= r0 && j0 >= r0 - (WIN-1))) s[nt][0] = -1e30f;
            if (!(j1 <= r0 && j1 >= r0 - (WIN-1))) s[nt][1] = -1e30f;
            if (!(j0 <= r1 && j0 >= r1 - (WIN-1))) s[nt][2] = -1e30f;
            if (!(j1 <= r1 && j1 >= r1 - (WIN-1))) s[nt][3] = -1e30f;
            mx0 = fmaxf(mx0, fmaxf(s[nt][0], s[nt][1]));
            mx1 = fmaxf(mx1, fmaxf(s[nt][2], s[nt][3]));
        }
        mx0 = fmaxf(mx0, __shfl_xor_sync(0xffffffffu, mx0, 1));
        mx0 = fmaxf(mx0, __shfl_xor_sync(0xffffffffu, mx0, 2));
        mx1 = fmaxf(mx1, __shfl_xor_sync(0xffffffffu, mx1, 1));
        mx1 = fmaxf(mx1, __shfl_xor_sync(0xffffffffu, mx1, 2));

        float mn0 = fmaxf(m0v, mx0), mn1 = fmaxf(m1v, mx1);
        float c0 = __expf(m0v - mn0), c1 = __expf(m1v - mn1);
        float rs0 = 0.f, rs1 = 0.f;
        #pragma unroll
        for (int nt = 0; nt < 8; nt++) {
            s[nt][0] = (s[nt][0] > -1e29f) ? __expf(s[nt][0] - mn0) : 0.f;
            s[nt][1] = (s[nt][1] > -1e29f) ? __expf(s[nt][1] - mn0) : 0.f;
            s[nt][2] = (s[nt][2] > -1e29f) ? __expf(s[nt][2] - mn1) : 0.f;
            s[nt][3] = (s[nt][3] > -1e29f) ? __expf(s[nt][3] - mn1) : 0.f;
            rs0 += s[nt][0] + s[nt][1];
            rs1 += s[nt][2] + s[nt][3];
        }
        rs0 += __shfl_xor_sync(0xffffffffu, rs0, 1);
        rs0 += __shfl_xor_sync(0xffffffffu, rs0, 2);
        rs1 += __shfl_xor_sync(0xffffffffu, rs1, 1);
        rs1 += __shfl_xor_sync(0xffffffffu, rs1, 2);
        l0 = l0*c0 + rs0;  l1 = l1*c1 + rs1;
        m0v = mn0;         m1v = mn1;
        #pragma unroll
        for (int nt = 0; nt < 8; nt++) {
            o[nt][0] *= c0; o[nt][1] *= c0;
            o[nt][2] *= c1; o[nt][3] *= c1;
        }

        __syncthreads();
        #pragma unroll
        for (int nt = 0; nt < 8; nt++) {
            unsigned* p0 = &Ks[(w16 + g    )*KST + nt*8 + 2*t4];
            unsigned* p1 = &Ks[(w16 + g + 8)*KST + nt*8 + 2*t4];
            p0[0] = f2tf32(s[nt][0]); p0[1] = f2tf32(s[nt][1]);
            p1[0] = f2tf32(s[nt][2]); p1[1] = f2tf32(s[nt][3]);
        }
        __syncwarp();

        #pragma unroll
        for (int ks = 0; ks < 8; ks++) {
            const int kb = ks*8;
            unsigned pa[4];
            pa[0] = Ks[(w16 + g    )*KST + kb + t4];
            pa[1] = Ks[(w16 + g + 8)*KST + kb + t4];
            pa[2] = Ks[(w16 + g    )*KST + kb + t4 + 4];
            pa[3] = Ks[(w16 + g + 8)*KST + kb + t4 + 4];
            #pragma unroll
            for (int nt = 0; nt < 8; nt++) {
                unsigned vb[2];
                vb[0] = Vs[(kb + t4    )*VST + nt*8 + g];
                vb[1] = Vs[(kb + t4 + 4)*VST + nt*8 + g];
                mma_tf32(o[nt], pa, vb);
            }
        }
    }

    const float inv0 = 1.0f / l0, inv1 = 1.0f / l1;
    float* out0 = &g_ao[(size_t)(b*T_ + r0)*D_ + h*DH];
    float* out1 = &g_ao[(size_t)(b*T_ + r1)*D_ + h*DH];
    #pragma unroll
    for (int nt = 0; nt < 8; nt++) {
        int d = nt*8 + 2*t4;
        *(float2*)&out0[d] = make_float2(tfr(o[nt][0]*inv0), tfr(o[nt][1]*inv0));
        *(float2*)&out1[d] = make_float2(tfr(o[nt][2]*inv1), tfr(o[nt][3]*inv1));
    }
}

// ---------------- launch ----------------
extern "C" void kernel_launch(void* const* d_in, const int* in_sizes, int n_in,
                              void* d_out, int out_size) {
    const float* query = (const float*)d_in[0];
    const float* Wq    = (const float*)d_in[1];
    const float* Wk    = (const float*)d_in[2];
    const float* Wv    = (const float*)d_in[3];
    const float* Wo    = (const float*)d_in[4];
    const float* bo    = (const float*)d_in[5];
    float* out = (float*)d_out;

    static int attr_done = 0;
    if (!attr_done) {
        cudaFuncSetAttribute(gemm_kernel<0>, cudaFuncAttributeMaxDynamicSharedMemorySize, SMEM_TOT);
        cudaFuncSetAttribute(gemm_kernel<1>, cudaFuncAttributeMaxDynamicSharedMemorySize, SMEM_TOT);
        attr_done = 1;
    }

    rope_table_kernel<<<(T_*32)/256, 256>>>();
    round_kernel<<<(M_*D_/4 + 255)/256, 256>>>((const float4*)query, (const float4*)Wq,
                                               (const float4*)Wk, (const float4*)Wv, (const float4*)Wo);
    gemm_kernel<0><<<dim3(24, M_/GBM), 256, SMEM_TOT>>>(nullptr, nullptr);
    attn_kernel<<<dim3(T_/64, H_, B_), 128>>>();
    gemm_kernel<1><<<dim3(8, M_/GBM), 256, SMEM_TOT>>>(bo, out);
}

// round 7
// speedup vs baseline: 2.3211x; 1.0134x over previous
#include <cuda_runtime.h>
#include <math.h>
#include <stdint.h>

#define B_   2
#define T_   2048
#define D_   1024
#define H_   16
#define DH   64
#define WIN  128
#define M_   (B_*T_)          // 4096
#define SM_SCALE 0.125f

// ---------------- scratch ----------------
__device__ __align__(16) float g_q[B_*H_*T_*DH];   // holds tf32(SM_SCALE * rope(q))
__device__ __align__(16) float g_k[B_*H_*T_*DH];   // holds tf32(rope(k))
__device__ __align__(16) float g_v[B_*H_*T_*DH];   // holds tf32(v)
__device__ __align__(16) float g_ao[B_*T_*D_];     // attn out, tf32-rounded
__device__ __align__(16) float g_qr[M_*D_];        // tf32-rounded query
__device__ __align__(16) float g_wr[4*D_*D_];      // tf32-rounded Wq,Wk,Wv,Wo
__device__ __align__(16) float g_cos[T_*32];
__device__ __align__(16) float g_sin[T_*32];

// ---------------- helpers ----------------
__device__ __forceinline__ unsigned f2tf32(float x) {
    unsigned r;
    asm("cvt.rna.tf32.f32 %0, %1;" : "=r"(r) : "f"(x));
    return r;
}
__device__ __forceinline__ float tfr(float x) { return __uint_as_float(f2tf32(x)); }

__device__ __forceinline__ uint32_t smem_u32(const void* p) {
    uint32_t a;
    asm("{ .reg .u64 t; cvta.to.shared.u64 t, %1; cvt.u32.u64 %0, t; }" : "=r"(a) : "l"(p));
    return a;
}

#define CP_ASYNC16(dst, src) \
    asm volatile("cp.async.cg.shared.global [%0], [%1], 16;" :: "r"(dst), "l"(src))
#define CP_COMMIT() asm volatile("cp.async.commit_group;" ::: "memory")
#define CP_WAIT1()  asm volatile("cp.async.wait_group 1;"  ::: "memory")

__device__ __forceinline__ void mma_tf32(float (&d)[4], const unsigned (&a)[4], const unsigned (&b)[2]) {
    asm volatile(
        "mma.sync.aligned.m16n8k8.row.col.f32.tf32.tf32.f32 "
        "{%0,%1,%2,%3}, {%4,%5,%6,%7}, {%8,%9}, {%0,%1,%2,%3};\n"
        : "+f"(d[0]), "+f"(d[1]), "+f"(d[2]), "+f"(d[3])
        : "r"(a[0]), "r"(a[1]), "r"(a[2]), "r"(a[3]), "r"(b[0]), "r"(b[1]));
}

// ---------------- fused: tf32 pre-round + RoPE table ----------------
__device__ __forceinline__ float4 rt4(float4 v) {
    return make_float4(tfr(v.x), tfr(v.y), tfr(v.z), tfr(v.w));
}
__global__ void round_rope_kernel(const float4* __restrict__ q, const float4* __restrict__ wq,
                                  const float4* __restrict__ wk, const float4* __restrict__ wv,
                                  const float4* __restrict__ wo) {
    int id = blockIdx.x*256 + threadIdx.x;
    float4* qr = (float4*)g_qr;
    float4* wr = (float4*)g_wr;
    const int WQ4 = D_*D_/4;
    if (id < T_*32) {
        int t = id >> 5, d = id & 31;
        double inv = exp((-2.0*(double)d/64.0) * log(10000.0));
        double a = (double)t * inv;
        g_cos[id] = (float)cos(a);
        g_sin[id] = (float)sin(a);
    }
    if (id < M_*D_/4) qr[id] = rt4(q[id]);
    if (id < WQ4) {
        wr[id        ] = rt4(wq[id]);
        wr[id +   WQ4] = rt4(wk[id]);
        wr[id + 2*WQ4] = rt4(wv[id]);
        wr[id + 3*WQ4] = rt4(wo[id]);
    }
}

// ---------------- cp.async 3-stage tf32 GEMM: C[m,n] = sum_k A[m,k] W[n,k] ----------------
#define GBM 128
#define GBN 128
#define GBK 32
#define NSTG 3
#define NCH  (D_/GBK)               // 32
#define SST  36
#define A_ELE (GBM*SST)
#define B_ELE (GBN*SST)
#define STG_BYTES ((A_ELE + B_ELE)*4)
#define SMEM_TOT (NSTG*STG_BYTES)

__device__ __forceinline__ void load_stage(uint32_t stg_b, const float* __restrict__ Aq,
                                           const float* __restrict__ Wm,
                                           int m0, int n0, int k0, int tid) {
    #pragma unroll
    for (int i = 0; i < 4; i++) {
        int id = tid + i*256;
        int row = id >> 3, c4 = (id & 7) << 2;
        uint32_t dst = stg_b + (uint32_t)(row*SST + c4)*4;
        CP_ASYNC16(dst, Aq + (size_t)(m0+row)*D_ + k0 + c4);
    }
    uint32_t bb = stg_b + A_ELE*4;
    #pragma unroll
    for (int i = 0; i < 4; i++) {
        int id = tid + i*256;
        int row = id >> 3, c4 = (id & 7) << 2;
        uint32_t dst = bb + (uint32_t)(row*SST + c4)*4;
        CP_ASYNC16(dst, Wm + (size_t)(n0+row)*D_ + k0 + c4);
    }
}

template<int MODE>
__global__ void __launch_bounds__(256, 2) gemm_kernel(const float* __restrict__ bias,
                                                      float* __restrict__ out) {
    extern __shared__ __align__(16) unsigned smem[];
    uint32_t sb = smem_u32(smem);

    const int tid  = threadIdx.x;
    const int lane = tid & 31;
    const int warp = tid >> 5;
    const int wm   = warp & 3;
    const int wn   = warp >> 2;
    const int g    = lane >> 2;
    const int tg   = lane & 3;

    const int m0   = blockIdx.y * GBM;
    const int nblk = blockIdx.x;

    int proj, n0;
    const float *Aptr, *W;
    if (MODE == 0) {
        proj = nblk >> 3;  n0 = (nblk & 7) * GBN;
        Aptr = g_qr;  W = g_wr + (size_t)proj * D_ * D_;
    } else {
        proj = 3;  n0 = nblk * GBN;
        Aptr = g_ao;  W = g_wr + (size_t)3 * D_ * D_;
    }

    float acc[2][8][4];
    #pragma unroll
    for (int i = 0; i < 2; i++)
        #pragma unroll
        for (int j = 0; j < 8; j++)
            #pragma unroll
            for (int k = 0; k < 4; k++) acc[i][j][k] = 0.f;

    load_stage(sb,             Aptr, W, m0, n0, 0,   tid); CP_COMMIT();
    load_stage(sb + STG_BYTES, Aptr, W, m0, n0, GBK, tid); CP_COMMIT();

    for (int kt = 0; kt < NCH; kt++) {
        CP_WAIT1();
        __syncthreads();
        const int c2 = kt + NSTG - 1;
        if (c2 < NCH) {
            int s2 = c2 % NSTG;
            load_stage(sb + s2*STG_BYTES, Aptr, W, m0, n0, c2*GBK, tid);
        }
        CP_COMMIT();

        const unsigned* As = smem + (kt % NSTG)*(A_ELE + B_ELE);
        const unsigned* Bs = As + A_ELE;

        #pragma unroll
        for (int ks = 0; ks < 4; ks++) {
            const int kb = ks*8;
            unsigned af[2][4], bf[8][2];
            #pragma unroll
            for (int mt = 0; mt < 2; mt++) {
                int rbase = wm*32 + mt*16;
                af[mt][0] = As[(rbase+g  )*SST + kb+tg  ];
                af[mt][1] = As[(rbase+g+8)*SST + kb+tg  ];
                af[mt][2] = As[(rbase+g  )*SST + kb+tg+4];
                af[mt][3] = As[(rbase+g+8)*SST + kb+tg+4];
            }
            #pragma unroll
            for (int nt = 0; nt < 8; nt++) {
                int cb = wn*64 + nt*8;
                bf[nt][0] = Bs[(cb+g)*SST + kb+tg  ];
                bf[nt][1] = Bs[(cb+g)*SST + kb+tg+4];
            }
            #pragma unroll
            for (int mt = 0; mt < 2; mt++)
                #pragma unroll
                for (int nt = 0; nt < 8; nt++)
                    mma_tf32(acc[mt][nt], af[mt], bf[nt]);
        }
    }

    // -------- epilogue (MODE 0 writes tf32-rounded values; q also folds SM_SCALE) --------
    #pragma unroll
    for (int mt = 0; mt < 2; mt++) {
        #pragma unroll
        for (int half = 0; half < 2; half++) {
            int m = m0 + wm*32 + mt*16 + g + half*8;
            int t = m & (T_-1), bb = m >> 11;
            if (MODE == 0) {
                int h = (n0 + wn*64) >> 6;
                float* dst = (proj == 0) ? g_q : (proj == 1) ? g_k : g_v;
                float* row = &dst[(((size_t)bb*H_ + h)*T_ + t)*DH];
                if (proj < 2) {
                    const float sc = (proj == 0) ? SM_SCALE : 1.0f;
                    #pragma unroll
                    for (int nt = 0; nt < 4; nt++) {
                        int d0 = nt*8 + 2*tg;
                        float2 cc = *(const float2*)&g_cos[t*32 + d0];
                        float2 ss = *(const float2*)&g_sin[t*32 + d0];
                        float x1a = acc[mt][nt  ][half*2], x1b = acc[mt][nt  ][half*2+1];
                        float x2a = acc[mt][nt+4][half*2], x2b = acc[mt][nt+4][half*2+1];
                        *(float2*)&row[d0]      = make_float2(tfr(sc*(x1a*cc.x - x2a*ss.x)),
                                                              tfr(sc*(x1b*cc.y - x2b*ss.y)));
                        *(float2*)&row[d0 + 32] = make_float2(tfr(sc*(x2a*cc.x + x1a*ss.x)),
                                                              tfr(sc*(x2b*cc.y + x1b*ss.y)));
                    }
                } else {
                    #pragma unroll
                    for (int nt = 0; nt < 8; nt++) {
                        int d0 = nt*8 + 2*tg;
                        *(float2*)&row[d0] = make_float2(tfr(acc[mt][nt][half*2]),
                                                         tfr(acc[mt][nt][half*2+1]));
                    }
                }
            } else {
                int ncol = n0 + wn*64;
                float* orow = &out[(size_t)m*D_ + ncol];
                #pragma unroll
                for (int nt = 0; nt < 8; nt++) {
                    int nl = nt*8 + 2*tg;
                    *(float2*)&orow[nl] = make_float2(acc[mt][nt][half*2]   + bias[ncol+nl],
                                                      acc[mt][nt][half*2+1] + bias[ncol+nl+1]);
                }
            }
        }
    }
}

// ---------------- tensor-core sliding-window attention ----------------
// inputs are pre-rounded tf32 bit patterns; no conversion in hot loop
#define KST 68
#define VST 72
#define ATTN_SMEM ((64*KST + 64*VST + 64*KST)*4)   // Ks + Vs + Ps = 53248 B

__global__ void __launch_bounds__(128) attn_kernel() {
    extern __shared__ __align__(16) unsigned smemA[];
    unsigned* Ks = smemA;                 // K chunk
    unsigned* Vs = Ks + 64*KST;           // V chunk
    unsigned* Ps = Vs + 64*VST;           // P (per-warp private rows)

    const int tid  = threadIdx.x;
    const int lane = tid & 31;
    const int warp = tid >> 5;
    const int g    = lane >> 2;
    const int t4   = lane & 3;

    const int b = blockIdx.z, h = blockIdx.y, qt = blockIdx.x;
    const int qstart = qt << 6;
    const int w16 = warp << 4;
    const int r0 = qstart + w16 + g;
    const int r1 = r0 + 8;
    const size_t bhbase = ((size_t)(b*H_ + h))*T_*DH;

    const unsigned* gq = (const unsigned*)g_q;
    const unsigned* gk = (const unsigned*)g_k;
    const unsigned* gv = (const unsigned*)g_v;

    // Q fragments: raw tf32 bits (scale pre-folded in epilogue)
    unsigned qf[8][4];
    {
        const unsigned* Q = &gq[bhbase + (size_t)(qstart + w16)*DH];
        #pragma unroll
        for (int ks = 0; ks < 8; ks++) {
            int kb = ks*8;
            qf[ks][0] = Q[(size_t)(g  )*DH + kb + t4    ];
            qf[ks][1] = Q[(size_t)(g+8)*DH + kb + t4    ];
            qf[ks][2] = Q[(size_t)(g  )*DH + kb + t4 + 4];
            qf[ks][3] = Q[(size_t)(g+8)*DH + kb + t4 + 4];
        }
    }

    float o[8][4];
    #pragma unroll
    for (int nt = 0; nt < 8; nt++)
        #pragma unroll
        for (int c = 0; c < 4; c++) o[nt][c] = 0.f;
    float m0v = -1e30f, m1v = -1e30f, l0 = 0.f, l1 = 0.f;

    const int clo = (qt >= 2) ? qt-2 : 0;
    for (int ck = clo; ck <= qt; ck++) {
        const int kstart = ck << 6;
        __syncthreads();   // all warps done with Ks (S) and Vs (PV) of previous chunk
        #pragma unroll
        for (int j = 0; j < 8; j++) {
            int id = tid + j*128;
            int pos = id >> 4, d4 = (id & 15) << 2;
            uint4 kv = *(const uint4*)&gk[bhbase + (size_t)(kstart+pos)*DH + d4];
            *(uint4*)&Ks[pos*KST + d4] = kv;
            uint4 vv = *(const uint4*)&gv[bhbase + (size_t)(kstart+pos)*DH + d4];
            *(uint4*)&Vs[pos*VST + d4] = vv;
        }
        __syncthreads();

        // S = Q K^T  (16 x 64 per warp)
        float s[8][4];
        #pragma unroll
        for (int nt = 0; nt < 8; nt++)
            #pragma unroll
            for (int c = 0; c < 4; c++) s[nt][c] = 0.f;
        #pragma unroll
        for (int ks = 0; ks < 8; ks++) {
            const int kb = ks*8;
            #pragma unroll
            for (int nt = 0; nt < 8; nt++) {
                unsigned bfrag[2];
                bfrag[0] = Ks[(nt*8 + g)*KST + kb + t4];
                bfrag[1] = Ks[(nt*8 + g)*KST + kb + t4 + 4];
                mma_tf32(s[nt], qf[ks], bfrag);
            }
        }

        // mask + online softmax
        float mx0 = -1e30f, mx1 = -1e30f;
        #pragma unroll
        for (int nt = 0; nt < 8; nt++) {
            int j0 = kstart + nt*8 + 2*t4;
            int j1 = j0 + 1;
            if (!(j0 <= r0 && j0 >= r0 - (WIN-1))) s[nt][0] = -1e30f;
            if (!(j1 <= r0 && j1 >= r0 - (WIN-1))) s[nt][1] = -1e30f;
            if (!(j0 <= r1 && j0 >= r1 - (WIN-1))) s[nt][2] = -1e30f;
            if (!(j1 <= r1 && j1 >= r1 - (WIN-1))) s[nt][3] = -1e30f;
            mx0 = fmaxf(mx0, fmaxf(s[nt][0], s[nt][1]));
            mx1 = fmaxf(mx1, fmaxf(s[nt][2], s[nt][3]));
        }
        mx0 = fmaxf(mx0, __shfl_xor_sync(0xffffffffu, mx0, 1));
        mx0 = fmaxf(mx0, __shfl_xor_sync(0xffffffffu, mx0, 2));
        mx1 = fmaxf(mx1, __shfl_xor_sync(0xffffffffu, mx1, 1));
        mx1 = fmaxf(mx1, __shfl_xor_sync(0xffffffffu, mx1, 2));

        float mn0 = fmaxf(m0v, mx0), mn1 = fmaxf(m1v, mx1);
        float c0 = __expf(m0v - mn0), c1 = __expf(m1v - mn1);
        float rs0 = 0.f, rs1 = 0.f;
        #pragma unroll
        for (int nt = 0; nt < 8; nt++) {
            s[nt][0] = (s[nt][0] > -1e29f) ? __expf(s[nt][0] - mn0) : 0.f;
            s[nt][1] = (s[nt][1] > -1e29f) ? __expf(s[nt][1] - mn0) : 0.f;
            s[nt][2] = (s[nt][2] > -1e29f) ? __expf(s[nt][2] - mn1) : 0.f;
            s[nt][3] = (s[nt][3] > -1e29f) ? __expf(s[nt][3] - mn1) : 0.f;
            rs0 += s[nt][0] + s[nt][1];
            rs1 += s[nt][2] + s[nt][3];
        }
        rs0 += __shfl_xor_sync(0xffffffffu, rs0, 1);
        rs0 += __shfl_xor_sync(0xffffffffu, rs0, 2);
        rs1 += __shfl_xor_sync(0xffffffffu, rs1, 1);
        rs1 += __shfl_xor_sync(0xffffffffu, rs1, 2);
        l0 = l0*c0 + rs0;  l1 = l1*c1 + rs1;
        m0v = mn0;         m1v = mn1;
        #pragma unroll
        for (int nt = 0; nt < 8; nt++) {
            o[nt][0] *= c0; o[nt][1] *= c0;
            o[nt][2] *= c1; o[nt][3] *= c1;
        }

        // write P to private buffer (own rows only) — no block sync needed
        #pragma unroll
        for (int nt = 0; nt < 8; nt++) {
            unsigned* p0 = &Ps[(w16 + g    )*KST + nt*8 + 2*t4];
            unsigned* p1 = &Ps[(w16 + g + 8)*KST + nt*8 + 2*t4];
            p0[0] = f2tf32(s[nt][0]); p0[1] = f2tf32(s[nt][1]);
            p1[0] = f2tf32(s[nt][2]); p1[1] = f2tf32(s[nt][3]);
        }
        __syncwarp();

        // O += P V
        #pragma unroll
        for (int ks = 0; ks < 8; ks++) {
            const int kb = ks*8;
            unsigned pa[4];
            pa[0] = Ps[(w16 + g    )*KST + kb + t4];
            pa[1] = Ps[(w16 + g + 8)*KST + kb + t4];
            pa[2] = Ps[(w16 + g    )*KST + kb + t4 + 4];
            pa[3] = Ps[(w16 + g + 8)*KST + kb + t4 + 4];
            #pragma unroll
            for (int nt = 0; nt < 8; nt++) {
                unsigned vb[2];
                vb[0] = Vs[(kb + t4    )*VST + nt*8 + g];
                vb[1] = Vs[(kb + t4 + 4)*VST + nt*8 + g];
                mma_tf32(o[nt], pa, vb);
            }
        }
    }

    const float inv0 = 1.0f / l0, inv1 = 1.0f / l1;
    float* out0 = &g_ao[(size_t)(b*T_ + r0)*D_ + h*DH];
    float* out1 = &g_ao[(size_t)(b*T_ + r1)*D_ + h*DH];
    #pragma unroll
    for (int nt = 0; nt < 8; nt++) {
        int d = nt*8 + 2*t4;
        *(float2*)&out0[d] = make_float2(tfr(o[nt][0]*inv0), tfr(o[nt][1]*inv0));
        *(float2*)&out1[d] = make_float2(tfr(o[nt][2]*inv1), tfr(o[nt][3]*inv1));
    }
}

// ---------------- launch ----------------
extern "C" void kernel_launch(void* const* d_in, const int* in_sizes, int n_in,
                              void* d_out, int out_size) {
    const float* query = (const float*)d_in[0];
    const float* Wq    = (const float*)d_in[1];
    const float* Wk    = (const float*)d_in[2];
    const float* Wv    = (const float*)d_in[3];
    const float* Wo    = (const float*)d_in[4];
    const float* bo    = (const float*)d_in[5];
    float* out = (float*)d_out;

    static int attr_done = 0;
    if (!attr_done) {
        cudaFuncSetAttribute(gemm_kernel<0>, cudaFuncAttributeMaxDynamicSharedMemorySize, SMEM_TOT);
        cudaFuncSetAttribute(gemm_kernel<1>, cudaFuncAttributeMaxDynamicSharedMemorySize, SMEM_TOT);
        cudaFuncSetAttribute(attn_kernel,   cudaFuncAttributeMaxDynamicSharedMemorySize, ATTN_SMEM);
        attr_done = 1;
    }

    round_rope_kernel<<<(M_*D_/4 + 255)/256, 256>>>((const float4*)query, (const float4*)Wq,
                                                    (const float4*)Wk, (const float4*)Wv,
                                                    (const float4*)Wo);
    gemm_kernel<0><<<dim3(24, M_/GBM), 256, SMEM_TOT>>>(nullptr, nullptr);
    attn_kernel<<<dim3(T_/64, H_, B_), 128, ATTN_SMEM>>>();
    gemm_kernel<1><<<dim3(8, M_/GBM), 256, SMEM_TOT>>>(bo, out);
}

// round 8
// speedup vs baseline: 3.6223x; 1.5606x over previous
#include <cuda_runtime.h>
#include <cuda_fp16.h>
#include <math.h>
#include <stdint.h>

#define B_   2
#define T_   2048
#define D_   1024
#define H_   16
#define DH   64
#define WIN  128
#define M_   (B_*T_)          // 4096
#define SM_SCALE 0.125f

// ---------------- scratch ----------------
__device__ __align__(16) float  g_q[B_*H_*T_*DH];   // tf32(SM_SCALE * rope(q))
__device__ __align__(16) float  g_k[B_*H_*T_*DH];   // tf32(rope(k))
__device__ __align__(16) float  g_v[B_*H_*T_*DH];   // tf32(v)
__device__ __align__(16) __half g_ao[M_*D_];        // attn out (fp16)
__device__ __align__(16) __half g_qh[M_*D_];        // fp16 query
__device__ __align__(16) __half g_wh[4*D_*D_];      // fp16 Wq,Wk,Wv,Wo
__device__ __align__(16) float  g_cos[T_*32];
__device__ __align__(16) float  g_sin[T_*32];

// ---------------- helpers ----------------
__device__ __forceinline__ unsigned f2tf32(float x) {
    unsigned r;
    asm("cvt.rna.tf32.f32 %0, %1;" : "=r"(r) : "f"(x));
    return r;
}
__device__ __forceinline__ float tfr(float x) { return __uint_as_float(f2tf32(x)); }

__device__ __forceinline__ uint32_t smem_u32(const void* p) {
    uint32_t a;
    asm("{ .reg .u64 t; cvta.to.shared.u64 t, %1; cvt.u32.u64 %0, t; }" : "=r"(a) : "l"(p));
    return a;
}

#define CP_ASYNC16(dst, src) \
    asm volatile("cp.async.cg.shared.global [%0], [%1], 16;" :: "r"(dst), "l"(src))
#define CP_COMMIT() asm volatile("cp.async.commit_group;" ::: "memory")
#define CP_WAIT1()  asm volatile("cp.async.wait_group 1;"  ::: "memory")

// fp16 mma m16n8k16, fp32 accum
__device__ __forceinline__ void mma_f16(float (&d)[4], const unsigned (&a)[4], const unsigned (&b)[2]) {
    asm volatile(
        "mma.sync.aligned.m16n8k16.row.col.f32.f16.f16.f32 "
        "{%0,%1,%2,%3}, {%4,%5,%6,%7}, {%8,%9}, {%0,%1,%2,%3};\n"
        : "+f"(d[0]), "+f"(d[1]), "+f"(d[2]), "+f"(d[3])
        : "r"(a[0]), "r"(a[1]), "r"(a[2]), "r"(a[3]), "r"(b[0]), "r"(b[1]));
}
// tf32 mma for attention
__device__ __forceinline__ void mma_tf32(float (&d)[4], const unsigned (&a)[4], const unsigned (&b)[2]) {
    asm volatile(
        "mma.sync.aligned.m16n8k8.row.col.f32.tf32.tf32.f32 "
        "{%0,%1,%2,%3}, {%4,%5,%6,%7}, {%8,%9}, {%0,%1,%2,%3};\n"
        : "+f"(d[0]), "+f"(d[1]), "+f"(d[2]), "+f"(d[3])
        : "r"(a[0]), "r"(a[1]), "r"(a[2]), "r"(a[3]), "r"(b[0]), "r"(b[1]));
}

// ---------------- fused: fp16 pre-round + RoPE table ----------------
__global__ void round_rope_kernel(const float4* __restrict__ q, const float4* __restrict__ wq,
                                  const float4* __restrict__ wk, const float4* __restrict__ wv,
                                  const float4* __restrict__ wo) {
    int id = blockIdx.x*256 + threadIdx.x;
    const int WQ4 = D_*D_/4;
    if (id < T_*32) {
        int t = id >> 5, d = id & 31;
        double inv = exp((-2.0*(double)d/64.0) * log(10000.0));
        double a = (double)t * inv;
        g_cos[id] = (float)cos(a);
        g_sin[id] = (float)sin(a);
    }
    if (id < M_*D_/4) {
        float4 v = q[id];
        *(__half2*)(g_qh + id*4)     = __floats2half2_rn(v.x, v.y);
        *(__half2*)(g_qh + id*4 + 2) = __floats2half2_rn(v.z, v.w);
    }
    if (id < WQ4) {
        float4 v0 = wq[id], v1 = wk[id], v2 = wv[id], v3 = wo[id];
        *(__half2*)(g_wh + id*4)              = __floats2half2_rn(v0.x, v0.y);
        *(__half2*)(g_wh + id*4 + 2)          = __floats2half2_rn(v0.z, v0.w);
        *(__half2*)(g_wh + (size_t)WQ4*4   + id*4)     = __floats2half2_rn(v1.x, v1.y);
        *(__half2*)(g_wh + (size_t)WQ4*4   + id*4 + 2) = __floats2half2_rn(v1.z, v1.w);
        *(__half2*)(g_wh + (size_t)WQ4*8   + id*4)     = __floats2half2_rn(v2.x, v2.y);
        *(__half2*)(g_wh + (size_t)WQ4*8   + id*4 + 2) = __floats2half2_rn(v2.z, v2.w);
        *(__half2*)(g_wh + (size_t)WQ4*12  + id*4)     = __floats2half2_rn(v3.x, v3.y);
        *(__half2*)(g_wh + (size_t)WQ4*12  + id*4 + 2) = __floats2half2_rn(v3.z, v3.w);
    }
}

// ---------------- fp16 cp.async 3-stage GEMM: C[m,n] = sum_k A[m,k] W[n,k] ----------------
// Tiles: BM=128, BN=128, BK=64 (rows: 64 halves = 128B data + 16B pad = 144B)
#define GBM 128
#define GBN 128
#define GBK 64
#define NSTG 3
#define NCH  (D_/GBK)                 // 16
#define SRB  144                      // smem row bytes
#define SRW  36                       // smem row stride in half2 (32-bit) words
#define TILE_WORDS (GBM*SRW)          // per-matrix words per stage (4608)
#define STG_BYTES (2*GBM*SRB)         // 36864
#define SMEM_TOT (NSTG*STG_BYTES)     // 110592

__device__ __forceinline__ void load_stage(uint32_t stg_b, const __half* __restrict__ Aq,
                                           const __half* __restrict__ Wm,
                                           int m0, int n0, int k0, int tid) {
    // A: 128 rows x 64 halves = 1024 x 16B chunks; 256 threads -> 4 each. Same for B.
    #pragma unroll
    for (int i = 0; i < 4; i++) {
        int id = tid + i*256;
        int row = id >> 3, ch = id & 7;
        uint32_t dst = stg_b + (uint32_t)(row*SRB + ch*16);
        CP_ASYNC16(dst, Aq + (size_t)(m0+row)*D_ + k0 + ch*8);
    }
    uint32_t bb = stg_b + GBM*SRB;
    #pragma unroll
    for (int i = 0; i < 4; i++) {
        int id = tid + i*256;
        int row = id >> 3, ch = id & 7;
        uint32_t dst = bb + (uint32_t)(row*SRB + ch*16);
        CP_ASYNC16(dst, Wm + (size_t)(n0+row)*D_ + k0 + ch*8);
    }
}

template<int MODE>
__global__ void __launch_bounds__(256, 2) gemm_kernel(const float* __restrict__ bias,
                                                      float* __restrict__ out) {
    extern __shared__ __align__(16) unsigned smem[];
    uint32_t sb = smem_u32(smem);

    const int tid  = threadIdx.x;
    const int lane = tid & 31;
    const int warp = tid >> 5;
    const int wm   = warp & 3;     // 4 warps along M
    const int wn   = warp >> 2;    // 2 warps along N
    const int g    = lane >> 2;
    const int tg   = lane & 3;

    const int m0   = blockIdx.y * GBM;
    const int nblk = blockIdx.x;

    int proj, n0;
    const __half *Aptr, *W;
    if (MODE == 0) {
        proj = nblk >> 3;  n0 = (nblk & 7) * GBN;
        Aptr = g_qh;  W = g_wh + (size_t)proj * D_ * D_;
    } else {
        proj = 3;  n0 = nblk * GBN;
        Aptr = g_ao;  W = g_wh + (size_t)3 * D_ * D_;
    }

    float acc[2][8][4];
    #pragma unroll
    for (int i = 0; i < 2; i++)
        #pragma unroll
        for (int j = 0; j < 8; j++)
            #pragma unroll
            for (int k = 0; k < 4; k++) acc[i][j][k] = 0.f;

    load_stage(sb,             Aptr, W, m0, n0, 0,   tid); CP_COMMIT();
    load_stage(sb + STG_BYTES, Aptr, W, m0, n0, GBK, tid); CP_COMMIT();

    for (int kt = 0; kt < NCH; kt++) {
        CP_WAIT1();
        __syncthreads();
        const int c2 = kt + NSTG - 1;
        if (c2 < NCH) {
            int s2 = c2 % NSTG;
            load_stage(sb + s2*STG_BYTES, Aptr, W, m0, n0, c2*GBK, tid);
        }
        CP_COMMIT();

        const unsigned* As = smem + (kt % NSTG)*(2*TILE_WORDS);
        const unsigned* Bs = As + TILE_WORDS;

        #pragma unroll
        for (int ks = 0; ks < 4; ks++) {          // 4 x K=16 per 64-K stage
            const int kb = ks*8;                  // half2-word offset within row
            unsigned af[2][4], bf[8][2];
            #pragma unroll
            for (int mt = 0; mt < 2; mt++) {
                int rbase = wm*32 + mt*16;
                af[mt][0] = As[(rbase+g  )*SRW + kb+tg  ];
                af[mt][1] = As[(rbase+g+8)*SRW + kb+tg  ];
                af[mt][2] = As[(rbase+g  )*SRW + kb+tg+4];
                af[mt][3] = As[(rbase+g+8)*SRW + kb+tg+4];
            }
            #pragma unroll
            for (int nt = 0; nt < 8; nt++) {
                int cb = wn*64 + nt*8;
                bf[nt][0] = Bs[(cb+g)*SRW + kb+tg  ];
                bf[nt][1] = Bs[(cb+g)*SRW + kb+tg+4];
            }
            #pragma unroll
            for (int mt = 0; mt < 2; mt++)
                #pragma unroll
                for (int nt = 0; nt < 8; nt++)
                    mma_f16(acc[mt][nt], af[mt], bf[nt]);
        }
    }

    // -------- epilogue --------
    #pragma unroll
    for (int mt = 0; mt < 2; mt++) {
        #pragma unroll
        for (int half = 0; half < 2; half++) {
            int m = m0 + wm*32 + mt*16 + g + half*8;
            int t = m & (T_-1), bb = m >> 11;
            if (MODE == 0) {
                int h = (n0 + wn*64) >> 6;
                float* dst = (proj == 0) ? g_q : (proj == 1) ? g_k : g_v;
                float* row = &dst[(((size_t)bb*H_ + h)*T_ + t)*DH];
                if (proj < 2) {
                    const float sc = (proj == 0) ? SM_SCALE : 1.0f;
                    #pragma unroll
                    for (int nt = 0; nt < 4; nt++) {
                        int d0 = nt*8 + 2*tg;
                        float2 cc = *(const float2*)&g_cos[t*32 + d0];
                        float2 ss = *(const float2*)&g_sin[t*32 + d0];
                        float x1a = acc[mt][nt  ][half*2], x1b = acc[mt][nt  ][half*2+1];
                        float x2a = acc[mt][nt+4][half*2], x2b = acc[mt][nt+4][half*2+1];
                        *(float2*)&row[d0]      = make_float2(tfr(sc*(x1a*cc.x - x2a*ss.x)),
                                                              tfr(sc*(x1b*cc.y - x2b*ss.y)));
                        *(float2*)&row[d0 + 32] = make_float2(tfr(sc*(x2a*cc.x + x1a*ss.x)),
                                                              tfr(sc*(x2b*cc.y + x1b*ss.y)));
                    }
                } else {
                    #pragma unroll
                    for (int nt = 0; nt < 8; nt++) {
                        int d0 = nt*8 + 2*tg;
                        *(float2*)&row[d0] = make_float2(tfr(acc[mt][nt][half*2]),
                                                         tfr(acc[mt][nt][half*2+1]));
                    }
                }
            } else {
                int ncol = n0 + wn*64;
                float* orow = &out[(size_t)m*D_ + ncol];
                #pragma unroll
                for (int nt = 0; nt < 8; nt++) {
                    int nl = nt*8 + 2*tg;
                    *(float2*)&orow[nl] = make_float2(acc[mt][nt][half*2]   + bias[ncol+nl],
                                                      acc[mt][nt][half*2+1] + bias[ncol+nl+1]);
                }
            }
        }
    }
}

// ---------------- tensor-core sliding-window attention (tf32, known-good) ----------------
#define KST 68
#define VST 72
#define ATTN_SMEM ((64*KST + 64*VST + 64*KST)*4)

__global__ void __launch_bounds__(128) attn_kernel() {
    extern __shared__ __align__(16) unsigned smemA[];
    unsigned* Ks = smemA;
    unsigned* Vs = Ks + 64*KST;
    unsigned* Ps = Vs + 64*VST;

    const int tid  = threadIdx.x;
    const int lane = tid & 31;
    const int warp = tid >> 5;
    const int g    = lane >> 2;
    const int t4   = lane & 3;

    const int b = blockIdx.z, h = blockIdx.y, qt = blockIdx.x;
    const int qstart = qt << 6;
    const int w16 = warp << 4;
    const int r0 = qstart + w16 + g;
    const int r1 = r0 + 8;
    const size_t bhbase = ((size_t)(b*H_ + h))*T_*DH;

    const unsigned* gq = (const unsigned*)g_q;
    const unsigned* gk = (const unsigned*)g_k;
    const unsigned* gv = (const unsigned*)g_v;

    unsigned qf[8][4];
    {
        const unsigned* Q = &gq[bhbase + (size_t)(qstart + w16)*DH];
        #pragma unroll
        for (int ks = 0; ks < 8; ks++) {
            int kb = ks*8;
            qf[ks][0] = Q[(size_t)(g  )*DH + kb + t4    ];
            qf[ks][1] = Q[(size_t)(g+8)*DH + kb + t4    ];
            qf[ks][2] = Q[(size_t)(g  )*DH + kb + t4 + 4];
            qf[ks][3] = Q[(size_t)(g+8)*DH + kb + t4 + 4];
        }
    }

    float o[8][4];
    #pragma unroll
    for (int nt = 0; nt < 8; nt++)
        #pragma unroll
        for (int c = 0; c < 4; c++) o[nt][c] = 0.f;
    float m0v = -1e30f, m1v = -1e30f, l0 = 0.f, l1 = 0.f;

    const int clo = (qt >= 2) ? qt-2 : 0;
    for (int ck = clo; ck <= qt; ck++) {
        const int kstart = ck << 6;
        __syncthreads();
        #pragma unroll
        for (int j = 0; j < 8; j++) {
            int id = tid + j*128;
            int pos = id >> 4, d4 = (id & 15) << 2;
            uint4 kv = *(const uint4*)&gk[bhbase + (size_t)(kstart+pos)*DH + d4];
            *(uint4*)&Ks[pos*KST + d4] = kv;
            uint4 vv = *(const uint4*)&gv[bhbase + (size_t)(kstart+pos)*DH + d4];
            *(uint4*)&Vs[pos*VST + d4] = vv;
        }
        __syncthreads();

        float s[8][4];
        #pragma unroll
        for (int nt = 0; nt < 8; nt++)
            #pragma unroll
            for (int c = 0; c < 4; c++) s[nt][c] = 0.f;
        #pragma unroll
        for (int ks = 0; ks < 8; ks++) {
            const int kb = ks*8;
            #pragma unroll
            for (int nt = 0; nt < 8; nt++) {
                unsigned bfrag[2];
                bfrag[0] = Ks[(nt*8 + g)*KST + kb + t4];
                bfrag[1] = Ks[(nt*8 + g)*KST + kb + t4 + 4];
                mma_tf32(s[nt], qf[ks], bfrag);
            }
        }

        float mx0 = -1e30f, mx1 = -1e30f;
        #pragma unroll
        for (int nt = 0; nt < 8; nt++) {
            int j0 = kstart + nt*8 + 2*t4;
            int j1 = j0 + 1;
            if (!(j0 <= r0 && j0 >= r0 - (WIN-1))) s[nt][0] = -1e30f;
            if (!(j1 <= r0 && j1 >= r0 - (WIN-1))) s[nt][1] = -1e30f;
            if (!(j0 <= r1 && j0 >= r1 - (WIN-1))) s[nt][2] = -1e30f;
            if (!(j1 <= r1 && j1 >= r1 - (WIN-1))) s[nt][3] = -1e30f;
            mx0 = fmaxf(mx0, fmaxf(s[nt][0], s[nt][1]));
            mx1 = fmaxf(mx1, fmaxf(s[nt][2], s[nt][3]));
        }
        mx0 = fmaxf(mx0, __shfl_xor_sync(0xffffffffu, mx0, 1));
        mx0 = fmaxf(mx0, __shfl_xor_sync(0xffffffffu, mx0, 2));
        mx1 = fmaxf(mx1, __shfl_xor_sync(0xffffffffu, mx1, 1));
        mx1 = fmaxf(mx1, __shfl_xor_sync(0xffffffffu, mx1, 2));

        float mn0 = fmaxf(m0v, mx0), mn1 = fmaxf(m1v, mx1);
        float c0 = __expf(m0v - mn0), c1 = __expf(m1v - mn1);
        float rs0 = 0.f, rs1 = 0.f;
        #pragma unroll
        for (int nt = 0; nt < 8; nt++) {
            s[nt][0] = (s[nt][0] > -1e29f) ? __expf(s[nt][0] - mn0) : 0.f;
            s[nt][1] = (s[nt][1] > -1e29f) ? __expf(s[nt][1] - mn0) : 0.f;
            s[nt][2] = (s[nt][2] > -1e29f) ? __expf(s[nt][2] - mn1) : 0.f;
            s[nt][3] = (s[nt][3] > -1e29f) ? __expf(s[nt][3] - mn1) : 0.f;
            rs0 += s[nt][0] + s[nt][1];
            rs1 += s[nt][2] + s[nt][3];
        }
        rs0 += __shfl_xor_sync(0xffffffffu, rs0, 1);
        rs0 += __shfl_xor_sync(0xffffffffu, rs0, 2);
        rs1 += __shfl_xor_sync(0xffffffffu, rs1, 1);
        rs1 += __shfl_xor_sync(0xffffffffu, rs1, 2);
        l0 = l0*c0 + rs0;  l1 = l1*c1 + rs1;
        m0v = mn0;         m1v = mn1;
        #pragma unroll
        for (int nt = 0; nt < 8; nt++) {
            o[nt][0] *= c0; o[nt][1] *= c0;
            o[nt][2] *= c1; o[nt][3] *= c1;
        }

        #pragma unroll
        for (int nt = 0; nt < 8; nt++) {
            unsigned* p0 = &Ps[(w16 + g    )*KST + nt*8 + 2*t4];
            unsigned* p1 = &Ps[(w16 + g + 8)*KST + nt*8 + 2*t4];
            p0[0] = f2tf32(s[nt][0]); p0[1] = f2tf32(s[nt][1]);
            p1[0] = f2tf32(s[nt][2]); p1[1] = f2tf32(s[nt][3]);
        }
        __syncwarp();

        #pragma unroll
        for (int ks = 0; ks < 8; ks++) {
            const int kb = ks*8;
            unsigned pa[4];
            pa[0] = Ps[(w16 + g    )*KST + kb + t4];
            pa[1] = Ps[(w16 + g + 8)*KST + kb + t4];
            pa[2] = Ps[(w16 + g    )*KST + kb + t4 + 4];
            pa[3] = Ps[(w16 + g + 8)*KST + kb + t4 + 4];
            #pragma unroll
            for (int nt = 0; nt < 8; nt++) {
                unsigned vb[2];
                vb[0] = Vs[(kb + t4    )*VST + nt*8 + g];
                vb[1] = Vs[(kb + t4 + 4)*VST + nt*8 + g];
                mma_tf32(o[nt], pa, vb);
            }
        }
    }

    const float inv0 = 1.0f / l0, inv1 = 1.0f / l1;
    __half* out0 = &g_ao[(size_t)(b*T_ + r0)*D_ + h*DH];
    __half* out1 = &g_ao[(size_t)(b*T_ + r1)*D_ + h*DH];
    #pragma unroll
    for (int nt = 0; nt < 8; nt++) {
        int d = nt*8 + 2*t4;
        *(__half2*)&out0[d] = __floats2half2_rn(o[nt][0]*inv0, o[nt][1]*inv0);
        *(__half2*)&out1[d] = __floats2half2_rn(o[nt][2]*inv1, o[nt][3]*inv1);
    }
}

// ---------------- launch ----------------
extern "C" void kernel_launch(void* const* d_in, const int* in_sizes, int n_in,
                              void* d_out, int out_size) {
    const float* query = (const float*)d_in[0];
    const float* Wq    = (const float*)d_in[1];
    const float* Wk    = (const float*)d_in[2];
    const float* Wv    = (const float*)d_in[3];
    const float* Wo    = (const float*)d_in[4];
    const float* bo    = (const float*)d_in[5];
    float* out = (float*)d_out;

    static int attr_done = 0;
    if (!attr_done) {
        cudaFuncSetAttribute(gemm_kernel<0>, cudaFuncAttributeMaxDynamicSharedMemorySize, SMEM_TOT);
        cudaFuncSetAttribute(gemm_kernel<1>, cudaFuncAttributeMaxDynamicSharedMemorySize, SMEM_TOT);
        cudaFuncSetAttribute(attn_kernel,   cudaFuncAttributeMaxDynamicSharedMemorySize, ATTN_SMEM);
        attr_done = 1;
    }

    round_rope_kernel<<<(M_*D_/4 + 255)/256, 256>>>((const float4*)query, (const float4*)Wq,
                                                    (const float4*)Wk, (const float4*)Wv,
                                                    (const float4*)Wo);
    gemm_kernel<0><<<dim3(24, M_/GBM), 256, SMEM_TOT>>>(nullptr, nullptr);
    attn_kernel<<<dim3(T_/64, H_, B_), 128, ATTN_SMEM>>>();
    gemm_kernel<1><<<dim3(8, M_/GBM), 256, SMEM_TOT>>>(bo, out);
}

// round 9
// speedup vs baseline: 4.2862x; 1.1833x over previous
#include <cuda_runtime.h>
#include <cuda_fp16.h>
#include <math.h>
#include <stdint.h>

#define B_   2
#define T_   2048
#define D_   1024
#define H_   16
#define DH   64
#define WIN  128
#define M_   (B_*T_)          // 4096
#define SM_SCALE 0.125f

// ---------------- scratch ----------------
__device__ __align__(16) __half g_q[B_*H_*T_*DH];   // fp16(SM_SCALE * rope(q))
__device__ __align__(16) __half g_k[B_*H_*T_*DH];   // fp16(rope(k))
__device__ __align__(16) float  g_v[B_*H_*T_*DH];   // tf32(v)
__device__ __align__(16) __half g_ao[M_*D_];        // attn out (fp16)
__device__ __align__(16) __half g_qh[M_*D_];        // fp16 query
__device__ __align__(16) __half g_wh[4*D_*D_];      // fp16 Wq,Wk,Wv,Wo
__device__ __align__(16) float  g_cos[T_*32];
__device__ __align__(16) float  g_sin[T_*32];

// ---------------- helpers ----------------
__device__ __forceinline__ unsigned f2tf32(float x) {
    unsigned r;
    asm("cvt.rna.tf32.f32 %0, %1;" : "=r"(r) : "f"(x));
    return r;
}
__device__ __forceinline__ float tfr(float x) { return __uint_as_float(f2tf32(x)); }

__device__ __forceinline__ uint32_t smem_u32(const void* p) {
    uint32_t a;
    asm("{ .reg .u64 t; cvta.to.shared.u64 t, %1; cvt.u32.u64 %0, t; }" : "=r"(a) : "l"(p));
    return a;
}

#define CP_ASYNC16(dst, src) \
    asm volatile("cp.async.cg.shared.global [%0], [%1], 16;" :: "r"(dst), "l"(src))
#define CP_COMMIT() asm volatile("cp.async.commit_group;" ::: "memory")
#define CP_WAIT1()  asm volatile("cp.async.wait_group 1;"  ::: "memory")

__device__ __forceinline__ void ldsm4(unsigned &r0, unsigned &r1, unsigned &r2, unsigned &r3, uint32_t a) {
    asm volatile("ldmatrix.sync.aligned.m8n8.x4.shared.b16 {%0,%1,%2,%3}, [%4];"
        : "=r"(r0), "=r"(r1), "=r"(r2), "=r"(r3) : "r"(a));
}

// fp16 mma m16n8k16, fp32 accum
__device__ __forceinline__ void mma_f16(float (&d)[4], const unsigned (&a)[4], const unsigned (&b)[2]) {
    asm volatile(
        "mma.sync.aligned.m16n8k16.row.col.f32.f16.f16.f32 "
        "{%0,%1,%2,%3}, {%4,%5,%6,%7}, {%8,%9}, {%0,%1,%2,%3};\n"
        : "+f"(d[0]), "+f"(d[1]), "+f"(d[2]), "+f"(d[3])
        : "r"(a[0]), "r"(a[1]), "r"(a[2]), "r"(a[3]), "r"(b[0]), "r"(b[1]));
}
// tf32 mma (attention PV)
__device__ __forceinline__ void mma_tf32(float (&d)[4], const unsigned (&a)[4], const unsigned (&b)[2]) {
    asm volatile(
        "mma.sync.aligned.m16n8k8.row.col.f32.tf32.tf32.f32 "
        "{%0,%1,%2,%3}, {%4,%5,%6,%7}, {%8,%9}, {%0,%1,%2,%3};\n"
        : "+f"(d[0]), "+f"(d[1]), "+f"(d[2]), "+f"(d[3])
        : "r"(a[0]), "r"(a[1]), "r"(a[2]), "r"(a[3]), "r"(b[0]), "r"(b[1]));
}

// ---------------- fused: fp16 pre-round + RoPE table ----------------
__global__ void round_rope_kernel(const float4* __restrict__ q, const float4* __restrict__ wq,
                                  const float4* __restrict__ wk, const float4* __restrict__ wv,
                                  const float4* __restrict__ wo) {
    int id = blockIdx.x*256 + threadIdx.x;
    const int WQ4 = D_*D_/4;
    if (id < T_*32) {
        int t = id >> 5, d = id & 31;
        double inv = exp((-2.0*(double)d/64.0) * log(10000.0));
        double a = (double)t * inv;
        g_cos[id] = (float)cos(a);
        g_sin[id] = (float)sin(a);
    }
    if (id < M_*D_/4) {
        float4 v = q[id];
        *(__half2*)(g_qh + id*4)     = __floats2half2_rn(v.x, v.y);
        *(__half2*)(g_qh + id*4 + 2) = __floats2half2_rn(v.z, v.w);
    }
    if (id < WQ4) {
        float4 v0 = wq[id], v1 = wk[id], v2 = wv[id], v3 = wo[id];
        *(__half2*)(g_wh + id*4)              = __floats2half2_rn(v0.x, v0.y);
        *(__half2*)(g_wh + id*4 + 2)          = __floats2half2_rn(v0.z, v0.w);
        *(__half2*)(g_wh + (size_t)WQ4*4  + id*4)     = __floats2half2_rn(v1.x, v1.y);
        *(__half2*)(g_wh + (size_t)WQ4*4  + id*4 + 2) = __floats2half2_rn(v1.z, v1.w);
        *(__half2*)(g_wh + (size_t)WQ4*8  + id*4)     = __floats2half2_rn(v2.x, v2.y);
        *(__half2*)(g_wh + (size_t)WQ4*8  + id*4 + 2) = __floats2half2_rn(v2.z, v2.w);
        *(__half2*)(g_wh + (size_t)WQ4*12 + id*4)     = __floats2half2_rn(v3.x, v3.y);
        *(__half2*)(g_wh + (size_t)WQ4*12 + id*4 + 2) = __floats2half2_rn(v3.z, v3.w);
    }
}

// ---------------- fp16 cp.async 3-stage GEMM (ldmatrix fragments) ----------------
#define GBM 128
#define GBN 128
#define GBK 64
#define NSTG 3
#define NCH  (D_/GBK)                 // 16
#define SRB  144                      // smem row bytes (128 data + 16 pad)
#define STG_BYTES (2*GBM*SRB)         // 36864
#define SMEM_TOT (NSTG*STG_BYTES)     // 110592

__device__ __forceinline__ void load_stage(uint32_t stg_b, const __half* __restrict__ Aq,
                                           const __half* __restrict__ Wm,
                                           int m0, int n0, int k0, int tid) {
    #pragma unroll
    for (int i = 0; i < 4; i++) {
        int id = tid + i*256;
        int row = id >> 3, ch = id & 7;
        uint32_t dst = stg_b + (uint32_t)(row*SRB + ch*16);
        CP_ASYNC16(dst, Aq + (size_t)(m0+row)*D_ + k0 + ch*8);
    }
    uint32_t bb = stg_b + GBM*SRB;
    #pragma unroll
    for (int i = 0; i < 4; i++) {
        int id = tid + i*256;
        int row = id >> 3, ch = id & 7;
        uint32_t dst = bb + (uint32_t)(row*SRB + ch*16);
        CP_ASYNC16(dst, Wm + (size_t)(n0+row)*D_ + k0 + ch*8);
    }
}

template<int MODE>
__global__ void __launch_bounds__(256, 2) gemm_kernel(const float* __restrict__ bias,
                                                      float* __restrict__ out) {
    extern __shared__ __align__(16) unsigned smem[];
    uint32_t sb = smem_u32(smem);

    const int tid  = threadIdx.x;
    const int lane = tid & 31;
    const int warp = tid >> 5;
    const int wm   = warp & 3;
    const int wn   = warp >> 2;
    const int g    = lane >> 2;
    const int tg   = lane & 3;

    // ldmatrix lane address components
    const int rowA  = wm*32 + (lane & 7) + ((lane >> 3) & 1)*8;
    const int koffA = (lane >> 4)*16;
    const int rowB  = wn*64 + ((lane >> 4) << 3) + (lane & 7);
    const int koffB = ((lane >> 3) & 1)*16;

    const int m0   = blockIdx.y * GBM;
    const int nblk = blockIdx.x;

    int proj, n0;
    const __half *Aptr, *W;
    if (MODE == 0) {
        proj = nblk >> 3;  n0 = (nblk & 7) * GBN;
        Aptr = g_qh;  W = g_wh + (size_t)proj * D_ * D_;
    } else {
        proj = 3;  n0 = nblk * GBN;
        Aptr = g_ao;  W = g_wh + (size_t)3 * D_ * D_;
    }

    float acc[2][8][4];
    #pragma unroll
    for (int i = 0; i < 2; i++)
        #pragma unroll
        for (int j = 0; j < 8; j++)
            #pragma unroll
            for (int k = 0; k < 4; k++) acc[i][j][k] = 0.f;

    load_stage(sb,             Aptr, W, m0, n0, 0,   tid); CP_COMMIT();
    load_stage(sb + STG_BYTES, Aptr, W, m0, n0, GBK, tid); CP_COMMIT();

    for (int kt = 0; kt < NCH; kt++) {
        CP_WAIT1();
        __syncthreads();
        const int c2 = kt + NSTG - 1;
        if (c2 < NCH) {
            int s2 = c2 % NSTG;
            load_stage(sb + s2*STG_BYTES, Aptr, W, m0, n0, c2*GBK, tid);
        }
        CP_COMMIT();

        const uint32_t stgb  = sb + (kt % NSTG)*STG_BYTES;
        const uint32_t abase = stgb + (uint32_t)(rowA*SRB + koffA);
        const uint32_t bbase = stgb + GBM*SRB + (uint32_t)(rowB*SRB + koffB);

        #pragma unroll
        for (int ks = 0; ks < 4; ks++) {          // 4 x K=16 per 64-K stage
            unsigned af[2][4], bf[8][2];
            ldsm4(af[0][0], af[0][1], af[0][2], af[0][3], abase + ks*32);
            ldsm4(af[1][0], af[1][1], af[1][2], af[1][3], abase + 16*SRB + ks*32);
            #pragma unroll
            for (int p = 0; p < 4; p++)
                ldsm4(bf[2*p][0], bf[2*p][1], bf[2*p+1][0], bf[2*p+1][1],
                      bbase + p*16*SRB + ks*32);
            #pragma unroll
            for (int mt = 0; mt < 2; mt++)
                #pragma unroll
                for (int nt = 0; nt < 8; nt++)
                    mma_f16(acc[mt][nt], af[mt], bf[nt]);
        }
    }

    // -------- epilogue --------
    #pragma unroll
    for (int mt = 0; mt < 2; mt++) {
        #pragma unroll
        for (int half = 0; half < 2; half++) {
            int m = m0 + wm*32 + mt*16 + g + half*8;
            int t = m & (T_-1), bb = m >> 11;
            if (MODE == 0) {
                int h = (n0 + wn*64) >> 6;
                if (proj < 2) {
                    __half* rowh = &((proj == 0) ? g_q : g_k)[(((size_t)bb*H_ + h)*T_ + t)*DH];
                    const float sc = (proj == 0) ? SM_SCALE : 1.0f;
                    #pragma unroll
                    for (int nt = 0; nt < 4; nt++) {
                        int d0 = nt*8 + 2*tg;
                        float2 cc = *(const float2*)&g_cos[t*32 + d0];
                        float2 ss = *(const float2*)&g_sin[t*32 + d0];
                        float x1a = acc[mt][nt  ][half*2], x1b = acc[mt][nt  ][half*2+1];
                        float x2a = acc[mt][nt+4][half*2], x2b = acc[mt][nt+4][half*2+1];
                        *(__half2*)&rowh[d0]      = __floats2half2_rn(sc*(x1a*cc.x - x2a*ss.x),
                                                                      sc*(x1b*cc.y - x2b*ss.y));
                        *(__half2*)&rowh[d0 + 32] = __floats2half2_rn(sc*(x2a*cc.x + x1a*ss.x),
                                                                      sc*(x2b*cc.y + x1b*ss.y));
                    }
                } else {
                    float* row = &g_v[(((size_t)bb*H_ + h)*T_ + t)*DH];
                    #pragma unroll
                    for (int nt = 0; nt < 8; nt++) {
                        int d0 = nt*8 + 2*tg;
                        *(float2*)&row[d0] = make_float2(tfr(acc[mt][nt][half*2]),
                                                         tfr(acc[mt][nt][half*2+1]));
                    }
                }
            } else {
                int ncol = n0 + wn*64;
                float* orow = &out[(size_t)m*D_ + ncol];
                #pragma unroll
                for (int nt = 0; nt < 8; nt++) {
                    int nl = nt*8 + 2*tg;
                    *(float2*)&orow[nl] = make_float2(acc[mt][nt][half*2]   + bias[ncol+nl],
                                                      acc[mt][nt][half*2+1] + bias[ncol+nl+1]);
                }
            }
        }
    }
}

// ---------------- sliding-window attention: fp16 QK^T, tf32 PV ----------------
#define KSW 36    // K smem row stride in uint (half2) words; 144B rows
#define VST 72    // V smem stride (floats)
#define PST 68    // P smem stride (floats)
#define ATTN_SMEM ((64*KSW + 64*VST + 64*PST)*4)   // 45056 B

__global__ void __launch_bounds__(128) attn_kernel() {
    extern __shared__ __align__(16) unsigned smemA[];
    unsigned* Ks = smemA;                 // K chunk, fp16 [pos][dh]
    unsigned* Vs = Ks + 64*KSW;           // V chunk, tf32 [pos][dh]
    unsigned* Ps = Vs + 64*VST;           // P, tf32 [row][key]
    const uint32_t sK = smem_u32(smemA);

    const int tid  = threadIdx.x;
    const int lane = tid & 31;
    const int warp = tid >> 5;
    const int g    = lane >> 2;
    const int t4   = lane & 3;

    const int b = blockIdx.z, h = blockIdx.y, qt = blockIdx.x;
    const int qstart = qt << 6;
    const int w16 = warp << 4;
    const int r0 = qstart + w16 + g;
    const int r1 = r0 + 8;
    const size_t bhrow = (size_t)(b*H_ + h)*T_;     // row index base

    // ldmatrix lane addressing for K fragments (B operand)
    const int rowBk  = ((lane >> 4) << 3) + (lane & 7);
    const int koffBk = ((lane >> 3) & 1)*16;

    // Q fragments: fp16, 4 k-steps of 16
    unsigned qf[4][4];
    {
        const unsigned* qw = (const unsigned*)g_q;
        size_t rb0 = (bhrow + qstart + w16 + g)*32;    // 32 words per row
        size_t rb1 = rb0 + 8*32;
        #pragma unroll
        for (int ks = 0; ks < 4; ks++) {
            int kb = ks*8;
            qf[ks][0] = qw[rb0 + kb + t4];
            qf[ks][1] = qw[rb1 + kb + t4];
            qf[ks][2] = qw[rb0 + kb + t4 + 4];
            qf[ks][3] = qw[rb1 + kb + t4 + 4];
        }
    }

    float o[8][4];
    #pragma unroll
    for (int nt = 0; nt < 8; nt++)
        #pragma unroll
        for (int c = 0; c < 4; c++) o[nt][c] = 0.f;
    float m0v = -1e30f, m1v = -1e30f, l0 = 0.f, l1 = 0.f;

    const int clo = (qt >= 2) ? qt-2 : 0;
    for (int ck = clo; ck <= qt; ck++) {
        const int kstart = ck << 6;
        __syncthreads();
        // K: 64 rows x 8 uint4 = 512 chunks; V: 64 rows x 16 float4 = 1024 chunks
        {
            const uint4* gk4 = (const uint4*)g_k;
            #pragma unroll
            for (int j = 0; j < 4; j++) {
                int id = tid + j*128;
                int pos = id >> 3, ch = id & 7;
                uint4 kv = gk4[(bhrow + kstart + pos)*8 + ch];
                *(uint4*)&Ks[pos*KSW + ch*4] = kv;
            }
            const uint4* gv4 = (const uint4*)g_v;
            #pragma unroll
            for (int j = 0; j < 8; j++) {
                int id = tid + j*128;
                int pos = id >> 4, ch = id & 15;
                uint4 vv = gv4[(bhrow + kstart + pos)*16 + ch];
                *(uint4*)&Vs[pos*VST + ch*4] = vv;
            }
        }
        __syncthreads();

        // S = Q K^T  (fp16, 4 k-steps)
        float s[8][4];
        #pragma unroll
        for (int nt = 0; nt < 8; nt++)
            #pragma unroll
            for (int c = 0; c < 4; c++) s[nt][c] = 0.f;
        #pragma unroll
        for (int ks = 0; ks < 4; ks++) {
            unsigned bf[8][2];
            #pragma unroll
            for (int p = 0; p < 4; p++)
                ldsm4(bf[2*p][0], bf[2*p][1], bf[2*p+1][0], bf[2*p+1][1],
                      sK + (uint32_t)((p*16 + rowBk)*144 + ks*32 + koffBk));
            #pragma unroll
            for (int nt = 0; nt < 8; nt++)
                mma_f16(s[nt], qf[ks], bf[nt]);
        }

        // mask + online softmax
        float mx0 = -1e30f, mx1 = -1e30f;
        #pragma unroll
        for (int nt = 0; nt < 8; nt++) {
            int j0 = kstart + nt*8 + 2*t4;
            int j1 = j0 + 1;
            if (!(j0 <= r0 && j0 >= r0 - (WIN-1))) s[nt][0] = -1e30f;
            if (!(j1 <= r0 && j1 >= r0 - (WIN-1))) s[nt][1] = -1e30f;
            if (!(j0 <= r1 && j0 >= r1 - (WIN-1))) s[nt][2] = -1e30f;
            if (!(j1 <= r1 && j1 >= r1 - (WIN-1))) s[nt][3] = -1e30f;
            mx0 = fmaxf(mx0, fmaxf(s[nt][0], s[nt][1]));
            mx1 = fmaxf(mx1, fmaxf(s[nt][2], s[nt][3]));
        }
        mx0 = fmaxf(mx0, __shfl_xor_sync(0xffffffffu, mx0, 1));
        mx0 = fmaxf(mx0, __shfl_xor_sync(0xffffffffu, mx0, 2));
        mx1 = fmaxf(mx1, __shfl_xor_sync(0xffffffffu, mx1, 1));
        mx1 = fmaxf(mx1, __shfl_xor_sync(0xffffffffu, mx1, 2));

        float mn0 = fmaxf(m0v, mx0), mn1 = fmaxf(m1v, mx1);
        float c0 = __expf(m0v - mn0), c1 = __expf(m1v - mn1);
        float rs0 = 0.f, rs1 = 0.f;
        #pragma unroll
        for (int nt = 0; nt < 8; nt++) {
            s[nt][0] = (s[nt][0] > -1e29f) ? __expf(s[nt][0] - mn0) : 0.f;
            s[nt][1] = (s[nt][1] > -1e29f) ? __expf(s[nt][1] - mn0) : 0.f;
            s[nt][2] = (s[nt][2] > -1e29f) ? __expf(s[nt][2] - mn1) : 0.f;
            s[nt][3] = (s[nt][3] > -1e29f) ? __expf(s[nt][3] - mn1) : 0.f;
            rs0 += s[nt][0] + s[nt][1];
            rs1 += s[nt][2] + s[nt][3];
        }
        rs0 += __shfl_xor_sync(0xffffffffu, rs0, 1);
        rs0 += __shfl_xor_sync(0xffffffffu, rs0, 2);
        rs1 += __shfl_xor_sync(0xffffffffu, rs1, 1);
        rs1 += __shfl_xor_sync(0xffffffffu, rs1, 2);
        l0 = l0*c0 + rs0;  l1 = l1*c1 + rs1;
        m0v = mn0;         m1v = mn1;
        #pragma unroll
        for (int nt = 0; nt < 8; nt++) {
            o[nt][0] *= c0; o[nt][1] *= c0;
            o[nt][2] *= c1; o[nt][3] *= c1;
        }

        // write P (tf32) to private rows
        #pragma unroll
        for (int nt = 0; nt < 8; nt++) {
            unsigned* p0 = &Ps[(w16 + g    )*PST + nt*8 + 2*t4];
            unsigned* p1 = &Ps[(w16 + g + 8)*PST + nt*8 + 2*t4];
            p0[0] = f2tf32(s[nt][0]); p0[1] = f2tf32(s[nt][1]);
            p1[0] = f2tf32(s[nt][2]); p1[1] = f2tf32(s[nt][3]);
        }
        __syncwarp();

        // O += P V (tf32)
        #pragma unroll
        for (int ks = 0; ks < 8; ks++) {
            const int kb = ks*8;
            unsigned pa[4];
            pa[0] = Ps[(w16 + g    )*PST + kb + t4];
            pa[1] = Ps[(w16 + g + 8)*PST + kb + t4];
            pa[2] = Ps[(w16 + g    )*PST + kb + t4 + 4];
            pa[3] = Ps[(w16 + g + 8)*PST + kb + t4 + 4];
            #pragma unroll
            for (int nt = 0; nt < 8; nt++) {
                unsigned vb[2];
                vb[0] = Vs[(kb + t4    )*VST + nt*8 + g];
                vb[1] = Vs[(kb + t4 + 4)*VST + nt*8 + g];
                mma_tf32(o[nt], pa, vb);
            }
        }
    }

    const float inv0 = 1.0f / l0, inv1 = 1.0f / l1;
    __half* out0 = &g_ao[(size_t)(b*T_ + r0)*D_ + h*DH];
    __half* out1 = &g_ao[(size_t)(b*T_ + r1)*D_ + h*DH];
    #pragma unroll
    for (int nt = 0; nt < 8; nt++) {
        int d = nt*8 + 2*t4;
        *(__half2*)&out0[d] = __floats2half2_rn(o[nt][0]*inv0, o[nt][1]*inv0);
        *(__half2*)&out1[d] = __floats2half2_rn(o[nt][2]*inv1, o[nt][3]*inv1);
    }
}

// ---------------- launch ----------------
extern "C" void kernel_launch(void* const* d_in, const int* in_sizes, int n_in,
                              void* d_out, int out_size) {
    const float* query = (const float*)d_in[0];
    const float* Wq    = (const float*)d_in[1];
    const float* Wk    = (const float*)d_in[2];
    const float* Wv    = (const float*)d_in[3];
    const float* Wo    = (const float*)d_in[4];
    const float* bo    = (const float*)d_in[5];
    float* out = (float*)d_out;

    static int attr_done = 0;
    if (!attr_done) {
        cudaFuncSetAttribute(gemm_kernel<0>, cudaFuncAttributeMaxDynamicSharedMemorySize, SMEM_TOT);
        cudaFuncSetAttribute(gemm_kernel<1>, cudaFuncAttributeMaxDynamicSharedMemorySize, SMEM_TOT);
        cudaFuncSetAttribute(attn_kernel,   cudaFuncAttributeMaxDynamicSharedMemorySize, ATTN_SMEM);
        attr_done = 1;
    }

    round_rope_kernel<<<(M_*D_/4 + 255)/256, 256>>>((const float4*)query, (const float4*)Wq,
                                                    (const float4*)Wk, (const float4*)Wv,
                                                    (const float4*)Wo);
    gemm_kernel<0><<<dim3(24, M_/GBM), 256, SMEM_TOT>>>(nullptr, nullptr);
    attn_kernel<<<dim3(T_/64, H_, B_), 128, ATTN_SMEM>>>();
    gemm_kernel<1><<<dim3(8, M_/GBM), 256, SMEM_TOT>>>(bo, out);
}